// round 8
// baseline (speedup 1.0000x reference)
#include <cuda_runtime.h>
#include <cuda_fp16.h>
#include <cstdint>
#include <math.h>

#define BB 4
#define TT 4096
#define CC 1024
#define EE 8
#define KKK 2
#define HH 4096
#define NN (BB*TT)
#define CAP 8192

#define BM 256
#define BN 128
#define BK 64                               // halves per stage (128B rows)
#define STAGES 3
#define A_BYTES (BM*128)                    // 32768
#define B_BYTES (BN*128)                    // 16384
#define STAGE_BYTES (A_BYTES + B_BYTES)     // 49152
#define SMEM_BYTES (STAGES*STAGE_BYTES)     // 147456

// ---------------- device scratch ----------------
__device__ int    g_cnt[EE];
__device__ float  g_imp[EE];
__device__ int    g_rows[EE*CAP];
__device__ int    g_tokrow[NN*KKK];
__device__ float  g_tv[NN*KKK];
__device__ __half g_hh[(size_t)EE*CAP*HH];     // intermediate (fp16)
__device__ float  g_o[(size_t)EE*CAP*CC];
__device__ __half g_xh[(size_t)NN*CC];         // fp16 x
__device__ __half g_w1h[(size_t)EE*CC*HH];     // w1^T: [e][n][k], fp16
__device__ __half g_w2h[(size_t)EE*HH*CC];     // w2^T: [e][n][k], fp16

__device__ __forceinline__ uint32_t pack_h2(float lo, float hi) {
    union { __half2 h; uint32_t u; } cv;
    cv.h = __floats2half2_rn(lo, hi);
    return cv.u;
}
__device__ __forceinline__ void cp16(uint32_t dst, const void* src) {
    asm volatile("cp.async.cg.shared.global [%0], [%1], 16;\n" :: "r"(dst), "l"(src));
}
__device__ __forceinline__ void cp_commit() {
    asm volatile("cp.async.commit_group;\n" ::: "memory");
}
template<int N> __device__ __forceinline__ void cp_wait() {
    asm volatile("cp.async.wait_group %0;\n" :: "n"(N) : "memory");
}
__device__ __forceinline__ void ldsm4(uint32_t& r0, uint32_t& r1, uint32_t& r2, uint32_t& r3,
                                      uint32_t addr) {
    asm volatile("ldmatrix.sync.aligned.m8n8.x4.shared.b16 {%0,%1,%2,%3}, [%4];"
        : "=r"(r0), "=r"(r1), "=r"(r2), "=r"(r3) : "r"(addr));
}

// ---------------- init ----------------
__global__ void init_k() {
    int i = threadIdx.x;
    if (i < EE) { g_cnt[i] = 0; g_imp[i] = 0.f; }
}

// ---------------- x -> fp16 ----------------
__global__ void cvt_h(const float4* __restrict__ src, uint4* __restrict__ dst, int n8) {
    int i = blockIdx.x * blockDim.x + threadIdx.x;
    if (i >= n8) return;
    float4 a = src[2*i], b = src[2*i+1];
    uint4 o;
    o.x = pack_h2(a.x, a.y);
    o.y = pack_h2(a.z, a.w);
    o.z = pack_h2(b.x, b.y);
    o.w = pack_h2(b.z, b.w);
    dst[i] = o;
}

// ---------------- weight transpose + fp16: [e][k][n] -> [e][n][k] ----------------
__global__ void tcvt_h(const float* __restrict__ src, __half* __restrict__ dst,
                       int Kd, int Nd) {
    __shared__ float t[32][33];
    int e = blockIdx.z;
    src += (size_t)e * Kd * Nd;
    dst += (size_t)e * Kd * Nd;
    int k0 = blockIdx.x * 32, n0 = blockIdx.y * 32;
    int tx = threadIdx.x & 31, ty = threadIdx.x >> 5;
#pragma unroll
    for (int i = 0; i < 32; i += 8)
        t[ty + i][tx] = src[(size_t)(k0 + ty + i) * Nd + n0 + tx];
    __syncthreads();
#pragma unroll
    for (int i = 0; i < 32; i += 8)
        dst[(size_t)(n0 + ty + i) * Kd + k0 + tx] = __float2half_rn(t[tx][ty + i]);
}

// ---------------- router ----------------
__global__ void router_k(const float* __restrict__ x,
                         const float* __restrict__ rw,
                         const float* __restrict__ rb) {
    int gw   = (int)((blockIdx.x * blockDim.x + threadIdx.x) >> 5);
    int lane = threadIdx.x & 31;
    if (gw >= NN) return;
    const float* xr = x + (size_t)gw * CC;

    float acc[EE];
#pragma unroll
    for (int e = 0; e < EE; e++) acc[e] = 0.f;
    for (int c = lane; c < CC; c += 32) {
        float xv = xr[c];
        const float* w = rw + c * EE;
#pragma unroll
        for (int e = 0; e < EE; e++) acc[e] = fmaf(xv, w[e], acc[e]);
    }
#pragma unroll
    for (int e = 0; e < EE; e++) {
#pragma unroll
        for (int off = 16; off; off >>= 1)
            acc[e] += __shfl_xor_sync(0xffffffffu, acc[e], off);
    }
    if (lane == 0) {
        float p[EE];
        float mx = -1e30f;
#pragma unroll
        for (int e = 0; e < EE; e++) { p[e] = acc[e] + rb[e]; mx = fmaxf(mx, p[e]); }
        float s = 0.f;
#pragma unroll
        for (int e = 0; e < EE; e++) { p[e] = expf(p[e] - mx); s += p[e]; }
        float inv = 1.f / s;
#pragma unroll
        for (int e = 0; e < EE; e++) p[e] *= inv;

        int i0 = 0;
#pragma unroll
        for (int e = 1; e < EE; e++) if (p[e] > p[i0]) i0 = e;
        int i1 = (i0 == 0) ? 1 : 0;
#pragma unroll
        for (int e = 0; e < EE; e++) if (e != i0 && p[e] > p[i1]) i1 = e;

        g_tv[gw*2]   = p[i0];
        g_tv[gw*2+1] = p[i1];
        int es[2] = { i0, i1 };
#pragma unroll
        for (int s2 = 0; s2 < 2; s2++) {
            int e = es[s2];
            int pos = atomicAdd(&g_cnt[e], 1);
            if (pos < CAP) {
                g_rows[e*CAP + pos]  = gw;
                g_tokrow[gw*2 + s2]  = e*CAP + pos;
            } else {
                g_tokrow[gw*2 + s2]  = -1;
            }
        }
#pragma unroll
        for (int e = 0; e < EE; e++) atomicAdd(&g_imp[e], p[e]);
    }
}

// ---------------- grouped GEMM, fp16 m16n8k16, 256x128 tile, 64x64 warp tile ----
// MODE 1: h = relu(gather(xh) @ w1h[e]^T + b1[e])  -> fp16
// MODE 2: o = h @ w2h[e]^T + b2[e]                  -> fp32
template<int MODE>
__global__ __launch_bounds__(256, 1)
void gemm_k(const float* __restrict__ bias) {
    constexpr int  Kdim  = (MODE == 1) ? CC : HH;
    constexpr int  outN  = (MODE == 1) ? HH : CC;
    constexpr int  ITERS = Kdim / BK;

    const __half* A  = (MODE == 1) ? g_xh : g_hh;
    const __half* Wt = (MODE == 1) ? g_w1h : g_w2h;

    int e   = blockIdx.z;
    int cnt = min(g_cnt[e], CAP);
    int m0  = blockIdx.y * BM;
    if (m0 >= cnt) return;
    int n0  = blockIdx.x * BN;

    extern __shared__ char smem[];
    __shared__ int arow[BM];

    int tid  = threadIdx.x;
    int lane = tid & 31, warp = tid >> 5;

    {
        int idx = m0 + tid;
        int g;
        if (MODE == 1) g = (idx < cnt) ? g_rows[e*CAP + idx] : 0;
        else           g = e*CAP + idx;
        arow[tid] = g;
    }
    __syncthreads();

    // ---- cp.async descriptors: 8 A chunks + 4 B chunks per thread (16B) ----
    int j  = tid & 7;
    int rT = tid >> 3;                 // 0..31, swizzle key rT&7 invariant under +32
    const __half* aptr[8]; uint32_t adst[8];
    const __half* bptr[4]; uint32_t bdst[4];
#pragma unroll
    for (int i = 0; i < 8; i++) {
        int r = rT + 32*i;
        aptr[i] = A + (size_t)arow[r] * Kdim + j*8;
        adst[i] = (uint32_t)(r*128 + ((j ^ (rT & 7)) << 4));
    }
#pragma unroll
    for (int i = 0; i < 4; i++) {
        int r = rT + 32*i;
        bptr[i] = Wt + ((size_t)e * outN + n0 + r) * Kdim + j*8;
        bdst[i] = (uint32_t)(A_BYTES + r*128 + ((j ^ (rT & 7)) << 4));
    }

    uint32_t smbase = (uint32_t)__cvta_generic_to_shared(smem);

    auto issue = [&](int stage) {
        uint32_t s = smbase + (uint32_t)stage * STAGE_BYTES;
#pragma unroll
        for (int i = 0; i < 8; i++) { cp16(s + adst[i], aptr[i]); aptr[i] += BK; }
#pragma unroll
        for (int i = 0; i < 4; i++) { cp16(s + bdst[i], bptr[i]); bptr[i] += BK; }
    };

    issue(0); cp_commit();
    issue(1); cp_commit();

    // ---- ldmatrix per-lane components ----
    int wm  = (warp & 3) * 64;         // 4 M groups
    int wn  = (warp >> 2) * 64;        // 2 N groups
    int r16 = lane & 15;
    int coff = lane >> 4;              // k-half select
    int sl7  = lane & 7;
    uint32_t aoff[4];
#pragma unroll
    for (int mt = 0; mt < 4; mt++)
        aoff[mt] = (uint32_t)((wm + mt*16 + r16) * 128);
    uint32_t boff[4];
#pragma unroll
    for (int p = 0; p < 4; p++)
        boff[p] = (uint32_t)(A_BYTES + (wn + p*16 + r16) * 128);

    float acc[4][8][4];
#pragma unroll
    for (int mt = 0; mt < 4; mt++)
#pragma unroll
        for (int nt = 0; nt < 8; nt++)
#pragma unroll
            for (int q = 0; q < 4; q++) acc[mt][nt][q] = 0.f;

    for (int it = 0; it < ITERS; ++it) {
        cp_wait<1>();
        __syncthreads();
        if (it + 2 < ITERS) issue((it + 2) % STAGES);
        cp_commit();

        uint32_t stg = smbase + (uint32_t)(it % STAGES) * STAGE_BYTES;

#pragma unroll
        for (int ks = 0; ks < BK; ks += 16) {
            const int c0 = (ks >> 3) + coff;
            const uint32_t csw = (uint32_t)((c0 ^ sl7) << 4);
            uint32_t af[4][4], bf[8][2];
#pragma unroll
            for (int mt = 0; mt < 4; mt++)
                ldsm4(af[mt][0], af[mt][1], af[mt][2], af[mt][3],
                      stg + aoff[mt] + csw);
#pragma unroll
            for (int p = 0; p < 4; p++)
                ldsm4(bf[2*p][0], bf[2*p+1][0], bf[2*p][1], bf[2*p+1][1],
                      stg + boff[p] + csw);
#pragma unroll
            for (int mt = 0; mt < 4; mt++)
#pragma unroll
                for (int nt = 0; nt < 8; nt++) {
                    asm volatile(
                        "mma.sync.aligned.m16n8k16.row.col.f32.f16.f16.f32 "
                        "{%0,%1,%2,%3}, {%4,%5,%6,%7}, {%8,%9}, {%0,%1,%2,%3};"
                        : "+f"(acc[mt][nt][0]), "+f"(acc[mt][nt][1]),
                          "+f"(acc[mt][nt][2]), "+f"(acc[mt][nt][3])
                        : "r"(af[mt][0]), "r"(af[mt][1]), "r"(af[mt][2]), "r"(af[mt][3]),
                          "r"(bf[nt][0]), "r"(bf[nt][1]));
                }
        }
    }

    // ---- epilogue ----
    int q  = lane & 3;
    int gg = lane >> 2;
#pragma unroll
    for (int mt = 0; mt < 4; mt++)
#pragma unroll
        for (int nt = 0; nt < 8; nt++) {
            int mrow = wm + mt*16 + gg;
            int col  = n0 + wn + nt*8 + 2*q;
            float bc0 = bias[e * outN + col];
            float bc1 = bias[e * outN + col + 1];
            float v00 = acc[mt][nt][0] + bc0;
            float v01 = acc[mt][nt][1] + bc1;
            float v10 = acc[mt][nt][2] + bc0;
            float v11 = acc[mt][nt][3] + bc1;
            size_t o0 = ((size_t)(e * CAP + m0 + mrow)) * outN + col;
            size_t o1 = o0 + (size_t)8 * outN;
            if (MODE == 1) {
                uint32_t h0 = pack_h2(fmaxf(v00, 0.f), fmaxf(v01, 0.f));
                uint32_t h1 = pack_h2(fmaxf(v10, 0.f), fmaxf(v11, 0.f));
                *(uint32_t*)(g_hh + o0) = h0;
                *(uint32_t*)(g_hh + o1) = h1;
            } else {
                g_o[o0] = v00; g_o[o0 + 1] = v01;
                g_o[o1] = v10; g_o[o1 + 1] = v11;
            }
        }
}

// ---------------- combine ----------------
__global__ void combine_k(float* __restrict__ out) {
    size_t i = (size_t)blockIdx.x * blockDim.x + threadIdx.x;
    if (i >= (size_t)NN * CC / 4) return;
    int t  = (int)(i / (CC / 4));
    int c  = (int)(i % (CC / 4)) * 4;
    float w = g_tv[t];
    int r0 = g_tokrow[t * 2];
    int r1 = g_tokrow[t * 2 + 1];
    float4 a = make_float4(0.f, 0.f, 0.f, 0.f);
    float4 b = make_float4(0.f, 0.f, 0.f, 0.f);
    if (r0 >= 0) a = *(const float4*)(g_o + (size_t)r0 * CC + c);
    if (r1 >= 0) b = *(const float4*)(g_o + (size_t)r1 * CC + c);
    float4 o;
    o.x = w * (a.x + b.x); o.y = w * (a.y + b.y);
    o.z = w * (a.z + b.z); o.w = w * (a.w + b.w);
    *(float4*)(out + (size_t)t * CC + c) = o;
}

// ---------------- aux loss ----------------
__global__ void aux_k(float* __restrict__ out, int out_size) {
    int lane = threadIdx.x;
    float v = 0.f;
    if (lane < EE)
        v = (g_imp[lane] / (float)NN) * ((float)g_cnt[lane] / (float)(NN * KKK));
#pragma unroll
    for (int off = 16; off; off >>= 1) v += __shfl_xor_sync(0xffffffffu, v, off);
    if (lane == 0) {
        if (out_size > NN * CC)     out[(size_t)NN * CC] = v;
        if (out_size - 1 > NN * CC) out[(size_t)out_size - 1] = v;
    }
}

// ---------------- launch ----------------
extern "C" void kernel_launch(void* const* d_in, const int* in_sizes, int n_in,
                              void* d_out, int out_size) {
    const float* x  = (const float*)d_in[0];
    const float* rw = (const float*)d_in[1];
    const float* rb = (const float*)d_in[2];
    const float* w1 = (const float*)d_in[3];
    const float* b1 = (const float*)d_in[4];
    const float* w2 = (const float*)d_in[5];
    const float* b2 = (const float*)d_in[6];
    float* out = (float*)d_out;

    cudaFuncSetAttribute(gemm_k<1>, cudaFuncAttributeMaxDynamicSharedMemorySize, SMEM_BYTES);
    cudaFuncSetAttribute(gemm_k<2>, cudaFuncAttributeMaxDynamicSharedMemorySize, SMEM_BYTES);

    __half* xh;  cudaGetSymbolAddress((void**)&xh,  g_xh);
    __half* w1h; cudaGetSymbolAddress((void**)&w1h, g_w1h);
    __half* w2h; cudaGetSymbolAddress((void**)&w2h, g_w2h);

    init_k<<<1, 32>>>();
    router_k<<<NN / 8, 256>>>(x, rw, rb);

    {
        int n8 = (int)((size_t)NN * CC / 8);
        cvt_h<<<(n8 + 255) / 256, 256>>>((const float4*)x, (uint4*)xh, n8);
    }
    tcvt_h<<<dim3(CC/32, HH/32, EE), 256>>>(w1, w1h, CC, HH);
    tcvt_h<<<dim3(HH/32, CC/32, EE), 256>>>(w2, w2h, HH, CC);

    gemm_k<1><<<dim3(HH / BN, CAP / BM, EE), 256, SMEM_BYTES>>>(b1);
    gemm_k<2><<<dim3(CC / BN, CAP / BM, EE), 256, SMEM_BYTES>>>(b2);
    combine_k<<<(int)(((size_t)NN * CC / 4 + 255) / 256), 256>>>(out);
    aux_k<<<1, 32>>>(out, out_size);
}

// round 9
// speedup vs baseline: 1.0686x; 1.0686x over previous
#include <cuda_runtime.h>
#include <cuda_fp16.h>
#include <cstdint>
#include <math.h>

#define BB 4
#define TT 4096
#define CC 1024
#define EE 8
#define KKK 2
#define HH 4096
#define NN (BB*TT)
#define CAP 8192

#define BM 128
#define BN 128
#define BK 64                               // halves per stage (128B rows)
#define STAGES 3
#define A_BYTES (BM*128)
#define B_BYTES (BN*128)
#define STAGE_BYTES (A_BYTES + B_BYTES)     // 32768
#define SMEM_BYTES (STAGES*STAGE_BYTES)     // 98304

// ---------------- device scratch ----------------
__device__ int    g_cnt[EE];
__device__ float  g_imp[EE];
__device__ int    g_rows[EE*CAP];
__device__ int    g_tokrow[NN*KKK];
__device__ float  g_tv[NN*KKK];
__device__ __half g_hh[(size_t)EE*CAP*HH];     // intermediate (fp16)
__device__ float  g_o[(size_t)EE*CAP*CC];
__device__ __half g_xh[(size_t)NN*CC];         // fp16 x
__device__ __half g_w1h[(size_t)EE*CC*HH];     // w1^T: [e][n][k], fp16
__device__ __half g_w2h[(size_t)EE*HH*CC];     // w2^T: [e][n][k], fp16

__device__ __forceinline__ uint32_t pack_h2(float lo, float hi) {
    union { __half2 h; uint32_t u; } cv;
    cv.h = __floats2half2_rn(lo, hi);
    return cv.u;
}
__device__ __forceinline__ void cp16(uint32_t dst, const void* src) {
    asm volatile("cp.async.cg.shared.global [%0], [%1], 16;\n" :: "r"(dst), "l"(src));
}
__device__ __forceinline__ void cp_commit() {
    asm volatile("cp.async.commit_group;\n" ::: "memory");
}
template<int N> __device__ __forceinline__ void cp_wait() {
    asm volatile("cp.async.wait_group %0;\n" :: "n"(N) : "memory");
}
__device__ __forceinline__ void ldsm4(uint32_t& r0, uint32_t& r1, uint32_t& r2, uint32_t& r3,
                                      uint32_t addr) {
    asm volatile("ldmatrix.sync.aligned.m8n8.x4.shared.b16 {%0,%1,%2,%3}, [%4];"
        : "=r"(r0), "=r"(r1), "=r"(r2), "=r"(r3) : "r"(addr));
}

// ---------------- init ----------------
__global__ void init_k() {
    int i = threadIdx.x;
    if (i < EE) { g_cnt[i] = 0; g_imp[i] = 0.f; }
}

// ---------------- x -> fp16 ----------------
__global__ void cvt_h(const float4* __restrict__ src, uint4* __restrict__ dst, int n8) {
    int i = blockIdx.x * blockDim.x + threadIdx.x;
    if (i >= n8) return;
    float4 a = src[2*i], b = src[2*i+1];
    uint4 o;
    o.x = pack_h2(a.x, a.y);
    o.y = pack_h2(a.z, a.w);
    o.z = pack_h2(b.x, b.y);
    o.w = pack_h2(b.z, b.w);
    dst[i] = o;
}

// ---------------- weight transpose + fp16 (vectorized stores) ----------------
// [e][k][n] -> [e][n][k].  Tile: 64 k x 32 n.  16B uint4 stores to dst.
__global__ void tcvt_h(const float* __restrict__ src, __half* __restrict__ dst,
                       int Kd, int Nd) {
    __shared__ __half t[32][80];               // pitch 160B (16B aligned)
    int e = blockIdx.z;
    src += (size_t)e * Kd * Nd;
    dst += (size_t)e * Kd * Nd;
    int k0 = blockIdx.x * 64, n0 = blockIdx.y * 32;
    int nn = threadIdx.x & 31, kk = threadIdx.x >> 5;   // kk 0..7
#pragma unroll
    for (int i = 0; i < 8; i++)
        t[nn][kk + 8*i] = __float2half_rn(src[(size_t)(k0 + kk + 8*i) * Nd + n0 + nn]);
    __syncthreads();
    int n = threadIdx.x >> 3, kc = (threadIdx.x & 7) * 8;
    uint4 o = *(const uint4*)&t[n][kc];
    *(uint4*)&dst[(size_t)(n0 + n) * Kd + k0 + kc] = o;
}

// ---------------- router ----------------
__global__ void router_k(const float* __restrict__ x,
                         const float* __restrict__ rw,
                         const float* __restrict__ rb) {
    int gw   = (int)((blockIdx.x * blockDim.x + threadIdx.x) >> 5);
    int lane = threadIdx.x & 31;
    if (gw >= NN) return;
    const float* xr = x + (size_t)gw * CC;

    float acc[EE];
#pragma unroll
    for (int e = 0; e < EE; e++) acc[e] = 0.f;
    for (int c = lane; c < CC; c += 32) {
        float xv = xr[c];
        const float* w = rw + c * EE;
#pragma unroll
        for (int e = 0; e < EE; e++) acc[e] = fmaf(xv, w[e], acc[e]);
    }
#pragma unroll
    for (int e = 0; e < EE; e++) {
#pragma unroll
        for (int off = 16; off; off >>= 1)
            acc[e] += __shfl_xor_sync(0xffffffffu, acc[e], off);
    }
    if (lane == 0) {
        float p[EE];
        float mx = -1e30f;
#pragma unroll
        for (int e = 0; e < EE; e++) { p[e] = acc[e] + rb[e]; mx = fmaxf(mx, p[e]); }
        float s = 0.f;
#pragma unroll
        for (int e = 0; e < EE; e++) { p[e] = expf(p[e] - mx); s += p[e]; }
        float inv = 1.f / s;
#pragma unroll
        for (int e = 0; e < EE; e++) p[e] *= inv;

        int i0 = 0;
#pragma unroll
        for (int e = 1; e < EE; e++) if (p[e] > p[i0]) i0 = e;
        int i1 = (i0 == 0) ? 1 : 0;
#pragma unroll
        for (int e = 0; e < EE; e++) if (e != i0 && p[e] > p[i1]) i1 = e;

        g_tv[gw*2]   = p[i0];
        g_tv[gw*2+1] = p[i1];
        int es[2] = { i0, i1 };
#pragma unroll
        for (int s2 = 0; s2 < 2; s2++) {
            int e = es[s2];
            int pos = atomicAdd(&g_cnt[e], 1);
            if (pos < CAP) {
                g_rows[e*CAP + pos]  = gw;
                g_tokrow[gw*2 + s2]  = e*CAP + pos;
            } else {
                g_tokrow[gw*2 + s2]  = -1;
            }
        }
#pragma unroll
        for (int e = 0; e < EE; e++) atomicAdd(&g_imp[e], p[e]);
    }
}

// ---------------- grouped GEMM, fp16 m16n8k16, double-buffered fragments ----
// MODE 1: h = relu(gather(xh) @ w1h[e]^T + b1[e])  -> fp16
// MODE 2: o = h @ w2h[e]^T + b2[e]                  -> fp32
template<int MODE>
__global__ __launch_bounds__(256, 2)
void gemm_k(const float* __restrict__ bias) {
    constexpr int  Kdim  = (MODE == 1) ? CC : HH;
    constexpr int  outN  = (MODE == 1) ? HH : CC;
    constexpr int  ITERS = Kdim / BK;

    const __half* A  = (MODE == 1) ? g_xh : g_hh;
    const __half* Wt = (MODE == 1) ? g_w1h : g_w2h;

    int e   = blockIdx.z;
    int cnt = min(g_cnt[e], CAP);
    int m0  = blockIdx.y * BM;
    if (m0 >= cnt) return;
    int n0  = blockIdx.x * BN;

    extern __shared__ char smem[];
    __shared__ int arow[BM];

    int tid  = threadIdx.x;
    int lane = tid & 31, warp = tid >> 5;

    if (tid < BM) {
        int idx = m0 + tid;
        int g;
        if (MODE == 1) g = (idx < cnt) ? g_rows[e*CAP + idx] : 0;
        else           g = e*CAP + idx;
        arow[tid] = g;
    }
    __syncthreads();

    // ---- cp.async bases (arrays collapsed to base + stride) ----
    int j  = tid & 7;
    int rT = tid >> 3;                 // 0..31
    uint32_t adst0 = (uint32_t)(rT*128 + ((j ^ (rT & 7)) << 4));
    const __half* Aj = A + j*8;
    const __half* Bj = Wt + ((size_t)e * outN + n0) * Kdim + j*8;

    uint32_t smbase = (uint32_t)__cvta_generic_to_shared(smem);

    auto issue = [&](int stage, int it) {
        uint32_t s = smbase + (uint32_t)stage * STAGE_BYTES + adst0;
        size_t koff = (size_t)it * BK;
#pragma unroll
        for (int i = 0; i < 4; i++) {
            int r = rT + 32*i;
            cp16(s + (uint32_t)i*4096, Aj + (size_t)arow[r] * Kdim + koff);
        }
        s += A_BYTES;
#pragma unroll
        for (int i = 0; i < 4; i++) {
            int r = rT + 32*i;
            cp16(s + (uint32_t)i*4096, Bj + (size_t)r * Kdim + koff);
        }
    };

    issue(0, 0); cp_commit();
    issue(1, 1); cp_commit();

    // ---- ldmatrix per-lane components ----
    int wm  = (warp & 3) * 32;
    int wn  = (warp >> 2) * 64;
    int r16 = lane & 15;
    int coff = lane >> 4;              // k-half select
    int sl7  = lane & 7;
    uint32_t aoff0 = (uint32_t)((wm + r16) * 128);
    uint32_t boff0 = (uint32_t)(A_BYTES + (wn + r16) * 128);

    float acc[2][8][4];
#pragma unroll
    for (int mt = 0; mt < 2; mt++)
#pragma unroll
        for (int nt = 0; nt < 8; nt++)
#pragma unroll
            for (int q = 0; q < 4; q++) acc[mt][nt][q] = 0.f;

    uint32_t af[2][2][4], bf[2][8][2];

    for (int it = 0; it < ITERS; ++it) {
        cp_wait<1>();
        __syncthreads();
        if (it + 2 < ITERS) issue((it + 2) % STAGES, it + 2);
        cp_commit();

        uint32_t stg = smbase + (uint32_t)(it % STAGES) * STAGE_BYTES;

        // prefetch step 0 into buffer 0
        {
            uint32_t csw = (uint32_t)((coff ^ sl7) << 4);
#pragma unroll
            for (int mt = 0; mt < 2; mt++)
                ldsm4(af[0][mt][0], af[0][mt][1], af[0][mt][2], af[0][mt][3],
                      stg + aoff0 + (uint32_t)mt*2048 + csw);
#pragma unroll
            for (int p = 0; p < 4; p++)
                ldsm4(bf[0][2*p][0], bf[0][2*p+1][0], bf[0][2*p][1], bf[0][2*p+1][1],
                      stg + boff0 + (uint32_t)p*2048 + csw);
        }

#pragma unroll
        for (int s4 = 0; s4 < 4; s4++) {
            int cur = s4 & 1, nxt = cur ^ 1;
            if (s4 < 3) {
                uint32_t csw = (uint32_t)(((2*(s4+1) + coff) ^ sl7) << 4);
#pragma unroll
                for (int mt = 0; mt < 2; mt++)
                    ldsm4(af[nxt][mt][0], af[nxt][mt][1], af[nxt][mt][2], af[nxt][mt][3],
                          stg + aoff0 + (uint32_t)mt*2048 + csw);
#pragma unroll
                for (int p = 0; p < 4; p++)
                    ldsm4(bf[nxt][2*p][0], bf[nxt][2*p+1][0], bf[nxt][2*p][1], bf[nxt][2*p+1][1],
                          stg + boff0 + (uint32_t)p*2048 + csw);
            }
#pragma unroll
            for (int mt = 0; mt < 2; mt++)
#pragma unroll
                for (int nt = 0; nt < 8; nt++) {
                    asm volatile(
                        "mma.sync.aligned.m16n8k16.row.col.f32.f16.f16.f32 "
                        "{%0,%1,%2,%3}, {%4,%5,%6,%7}, {%8,%9}, {%0,%1,%2,%3};"
                        : "+f"(acc[mt][nt][0]), "+f"(acc[mt][nt][1]),
                          "+f"(acc[mt][nt][2]), "+f"(acc[mt][nt][3])
                        : "r"(af[cur][mt][0]), "r"(af[cur][mt][1]),
                          "r"(af[cur][mt][2]), "r"(af[cur][mt][3]),
                          "r"(bf[cur][nt][0]), "r"(bf[cur][nt][1]));
                }
        }
    }

    // ---- epilogue ----
    int q  = lane & 3;
    int gg = lane >> 2;
#pragma unroll
    for (int mt = 0; mt < 2; mt++)
#pragma unroll
        for (int nt = 0; nt < 8; nt++) {
            int mrow = wm + mt*16 + gg;
            int col  = n0 + wn + nt*8 + 2*q;
            float bc0 = bias[e * outN + col];
            float bc1 = bias[e * outN + col + 1];
            float v00 = acc[mt][nt][0] + bc0;
            float v01 = acc[mt][nt][1] + bc1;
            float v10 = acc[mt][nt][2] + bc0;
            float v11 = acc[mt][nt][3] + bc1;
            size_t o0 = ((size_t)(e * CAP + m0 + mrow)) * outN + col;
            size_t o1 = o0 + (size_t)8 * outN;
            if (MODE == 1) {
                uint32_t h0 = pack_h2(fmaxf(v00, 0.f), fmaxf(v01, 0.f));
                uint32_t h1 = pack_h2(fmaxf(v10, 0.f), fmaxf(v11, 0.f));
                *(uint32_t*)(g_hh + o0) = h0;
                *(uint32_t*)(g_hh + o1) = h1;
            } else {
                g_o[o0] = v00; g_o[o0 + 1] = v01;
                g_o[o1] = v10; g_o[o1 + 1] = v11;
            }
        }
}

// ---------------- combine ----------------
__global__ void combine_k(float* __restrict__ out) {
    size_t i = (size_t)blockIdx.x * blockDim.x + threadIdx.x;
    if (i >= (size_t)NN * CC / 4) return;
    int t  = (int)(i / (CC / 4));
    int c  = (int)(i % (CC / 4)) * 4;
    float w = g_tv[t];
    int r0 = g_tokrow[t * 2];
    int r1 = g_tokrow[t * 2 + 1];
    float4 a = make_float4(0.f, 0.f, 0.f, 0.f);
    float4 b = make_float4(0.f, 0.f, 0.f, 0.f);
    if (r0 >= 0) a = *(const float4*)(g_o + (size_t)r0 * CC + c);
    if (r1 >= 0) b = *(const float4*)(g_o + (size_t)r1 * CC + c);
    float4 o;
    o.x = w * (a.x + b.x); o.y = w * (a.y + b.y);
    o.z = w * (a.z + b.z); o.w = w * (a.w + b.w);
    *(float4*)(out + (size_t)t * CC + c) = o;
}

// ---------------- aux loss ----------------
__global__ void aux_k(float* __restrict__ out, int out_size) {
    int lane = threadIdx.x;
    float v = 0.f;
    if (lane < EE)
        v = (g_imp[lane] / (float)NN) * ((float)g_cnt[lane] / (float)(NN * KKK));
#pragma unroll
    for (int off = 16; off; off >>= 1) v += __shfl_xor_sync(0xffffffffu, v, off);
    if (lane == 0) {
        if (out_size > NN * CC)     out[(size_t)NN * CC] = v;
        if (out_size - 1 > NN * CC) out[(size_t)out_size - 1] = v;
    }
}

// ---------------- launch ----------------
extern "C" void kernel_launch(void* const* d_in, const int* in_sizes, int n_in,
                              void* d_out, int out_size) {
    const float* x  = (const float*)d_in[0];
    const float* rw = (const float*)d_in[1];
    const float* rb = (const float*)d_in[2];
    const float* w1 = (const float*)d_in[3];
    const float* b1 = (const float*)d_in[4];
    const float* w2 = (const float*)d_in[5];
    const float* b2 = (const float*)d_in[6];
    float* out = (float*)d_out;

    cudaFuncSetAttribute(gemm_k<1>, cudaFuncAttributeMaxDynamicSharedMemorySize, SMEM_BYTES);
    cudaFuncSetAttribute(gemm_k<2>, cudaFuncAttributeMaxDynamicSharedMemorySize, SMEM_BYTES);

    __half* xh;  cudaGetSymbolAddress((void**)&xh,  g_xh);
    __half* w1h; cudaGetSymbolAddress((void**)&w1h, g_w1h);
    __half* w2h; cudaGetSymbolAddress((void**)&w2h, g_w2h);

    init_k<<<1, 32>>>();
    router_k<<<NN / 8, 256>>>(x, rw, rb);

    {
        int n8 = (int)((size_t)NN * CC / 8);
        cvt_h<<<(n8 + 255) / 256, 256>>>((const float4*)x, (uint4*)xh, n8);
    }
    tcvt_h<<<dim3(CC/64, HH/32, EE), 256>>>(w1, w1h, CC, HH);
    tcvt_h<<<dim3(HH/64, CC/32, EE), 256>>>(w2, w2h, HH, CC);

    gemm_k<1><<<dim3(HH / BN, CAP / BM, EE), 256, SMEM_BYTES>>>(b1);
    gemm_k<2><<<dim3(CC / BN, CAP / BM, EE), 256, SMEM_BYTES>>>(b2);
    combine_k<<<(int)(((size_t)NN * CC / 4 + 255) / 256), 256>>>(out);
    aux_k<<<1, 32>>>(out, out_size);
}

// round 10
// speedup vs baseline: 1.1211x; 1.0491x over previous
#include <cuda_runtime.h>
#include <cuda_fp16.h>
#include <cstdint>
#include <math.h>

#define BB 4
#define TT 4096
#define CC 1024
#define EE 8
#define KKK 2
#define HH 4096
#define NN (BB*TT)
#define CAP 8192

#define BM 128
#define BN 128
#define BK 64                               // k-depth per stage
#define STAGES 3
#define A_BYTES (BM*128)                    // 128 token-rows x 128B (64 halves)
#define B_BYTES (BK*256)                    // 64 k-rows x 256B (128 halves)
#define STAGE_BYTES (A_BYTES + B_BYTES)     // 32768
#define SMEM_BYTES (STAGES*STAGE_BYTES)     // 98304

// ---------------- device scratch ----------------
__device__ int    g_cnt[EE];
__device__ float  g_imp[EE];
__device__ int    g_rows[EE*CAP];
__device__ int    g_tokrow[NN*KKK];
__device__ float  g_tv[NN*KKK];
__device__ __half g_hh[(size_t)EE*CAP*HH];     // intermediate (fp16)
__device__ __half g_xh[(size_t)NN*CC];         // fp16 x
__device__ __half g_w1h[(size_t)EE*CC*HH];     // fp16 w1, native [e][k=C][n=H]
__device__ __half g_w2h[(size_t)EE*HH*CC];     // fp16 w2, native [e][k=H][n=C]

__device__ __forceinline__ uint32_t pack_h2(float lo, float hi) {
    union { __half2 h; uint32_t u; } cv;
    cv.h = __floats2half2_rn(lo, hi);
    return cv.u;
}
__device__ __forceinline__ void cp16(uint32_t dst, const void* src) {
    asm volatile("cp.async.cg.shared.global [%0], [%1], 16;\n" :: "r"(dst), "l"(src));
}
__device__ __forceinline__ void cp_commit() {
    asm volatile("cp.async.commit_group;\n" ::: "memory");
}
template<int N> __device__ __forceinline__ void cp_wait() {
    asm volatile("cp.async.wait_group %0;\n" :: "n"(N) : "memory");
}
__device__ __forceinline__ void ldsm4(uint32_t& r0, uint32_t& r1, uint32_t& r2, uint32_t& r3,
                                      uint32_t addr) {
    asm volatile("ldmatrix.sync.aligned.m8n8.x4.shared.b16 {%0,%1,%2,%3}, [%4];"
        : "=r"(r0), "=r"(r1), "=r"(r2), "=r"(r3) : "r"(addr));
}
__device__ __forceinline__ void ldsm4t(uint32_t& r0, uint32_t& r1, uint32_t& r2, uint32_t& r3,
                                       uint32_t addr) {
    asm volatile("ldmatrix.sync.aligned.m8n8.x4.trans.shared.b16 {%0,%1,%2,%3}, [%4];"
        : "=r"(r0), "=r"(r1), "=r"(r2), "=r"(r3) : "r"(addr));
}

// ---------------- init ----------------
__global__ void init_k() {
    int i = threadIdx.x;
    if (i < EE) { g_cnt[i] = 0; g_imp[i] = 0.f; }
}

// ---------------- fp32 -> fp16 streaming convert ----------------
__global__ void cvt_h(const float4* __restrict__ src, uint4* __restrict__ dst, int n8) {
    int i = blockIdx.x * blockDim.x + threadIdx.x;
    if (i >= n8) return;
    float4 a = src[2*i], b = src[2*i+1];
    uint4 o;
    o.x = pack_h2(a.x, a.y);
    o.y = pack_h2(a.z, a.w);
    o.z = pack_h2(b.x, b.y);
    o.w = pack_h2(b.z, b.w);
    dst[i] = o;
}

// ---------------- router ----------------
__global__ void router_k(const float* __restrict__ x,
                         const float* __restrict__ rw,
                         const float* __restrict__ rb) {
    int gw   = (int)((blockIdx.x * blockDim.x + threadIdx.x) >> 5);
    int lane = threadIdx.x & 31;
    if (gw >= NN) return;
    const float* xr = x + (size_t)gw * CC;

    float acc[EE];
#pragma unroll
    for (int e = 0; e < EE; e++) acc[e] = 0.f;
    for (int c = lane; c < CC; c += 32) {
        float xv = xr[c];
        const float* w = rw + c * EE;
#pragma unroll
        for (int e = 0; e < EE; e++) acc[e] = fmaf(xv, w[e], acc[e]);
    }
#pragma unroll
    for (int e = 0; e < EE; e++) {
#pragma unroll
        for (int off = 16; off; off >>= 1)
            acc[e] += __shfl_xor_sync(0xffffffffu, acc[e], off);
    }
    if (lane == 0) {
        float p[EE];
        float mx = -1e30f;
#pragma unroll
        for (int e = 0; e < EE; e++) { p[e] = acc[e] + rb[e]; mx = fmaxf(mx, p[e]); }
        float s = 0.f;
#pragma unroll
        for (int e = 0; e < EE; e++) { p[e] = expf(p[e] - mx); s += p[e]; }
        float inv = 1.f / s;
#pragma unroll
        for (int e = 0; e < EE; e++) p[e] *= inv;

        int i0 = 0;
#pragma unroll
        for (int e = 1; e < EE; e++) if (p[e] > p[i0]) i0 = e;
        int i1 = (i0 == 0) ? 1 : 0;
#pragma unroll
        for (int e = 0; e < EE; e++) if (e != i0 && p[e] > p[i1]) i1 = e;

        g_tv[gw*2]   = p[i0];
        g_tv[gw*2+1] = p[i1];
        int es[2] = { i0, i1 };
#pragma unroll
        for (int s2 = 0; s2 < 2; s2++) {
            int e = es[s2];
            int pos = atomicAdd(&g_cnt[e], 1);
            if (pos < CAP) {
                g_rows[e*CAP + pos]  = gw;
                g_tokrow[gw*2 + s2]  = e*CAP + pos;
            } else {
                g_tokrow[gw*2 + s2]  = -1;
            }
        }
#pragma unroll
        for (int e = 0; e < EE; e++) atomicAdd(&g_imp[e], p[e]);
    }
}

// ---------------- grouped GEMM, fp16 m16n8k16, B via ldmatrix.trans ----------
// MODE 1: h = relu(gather(xh) @ w1[e] + b1[e])  -> fp16 (g_hh)
// MODE 2: out[tok] += w_tok * (h @ w2[e] + b2[e])   (atomic combine)
template<int MODE>
__global__ __launch_bounds__(256, 2)
void gemm_k(const float* __restrict__ bias, float* __restrict__ out) {
    constexpr int  Kdim  = (MODE == 1) ? CC : HH;
    constexpr int  outN  = (MODE == 1) ? HH : CC;
    constexpr int  ITERS = Kdim / BK;

    const __half* A = (MODE == 1) ? g_xh : g_hh;
    const __half* W = (MODE == 1) ? g_w1h : g_w2h;

    int e   = blockIdx.z;
    int cnt = min(g_cnt[e], CAP);
    int m0  = blockIdx.y * BM;
    if (m0 >= cnt) return;
    int n0  = blockIdx.x * BN;

    extern __shared__ char smem[];
    __shared__ int arow[BM];   // MODE1: gather row (token). MODE2: token or -1.

    int tid  = threadIdx.x;
    int lane = tid & 31, warp = tid >> 5;

    if (tid < BM) {
        int idx = m0 + tid;
        if (MODE == 1) arow[tid] = (idx < cnt) ? g_rows[e*CAP + idx] : 0;
        else           arow[tid] = (idx < cnt) ? g_rows[e*CAP + idx] : -1;
    }
    __syncthreads();

    // ---- cp.async descriptors ----
    // A: 128 rows x 8 chunks(16B); swizzle chunk j ^ (row&7)
    int j  = tid & 7;
    int rT = tid >> 3;                 // 0..31
    uint32_t adst0 = (uint32_t)(rT*128 + ((j ^ (rT & 7)) << 4));
    const __half* Aj = A + j*8;
    // B: 64 k-rows x 16 slots(16B); swizzle slot j2 ^ (k&7)
    int j2 = tid & 15;
    int rB = tid >> 4;                 // 0..15
    uint32_t bdst0 = (uint32_t)(A_BYTES + rB*256 + ((j2 ^ (rB & 7)) << 4));
    const __half* Bj = W + (size_t)e * Kdim * outN + n0 + j2*8;

    uint32_t smbase = (uint32_t)__cvta_generic_to_shared(smem);

    auto issue = [&](int stage, int it) {
        uint32_t s = smbase + (uint32_t)stage * STAGE_BYTES;
        size_t koff = (size_t)it * BK;
#pragma unroll
        for (int i = 0; i < 4; i++) {
            int r = rT + 32*i;
            size_t ar = (MODE == 1) ? (size_t)arow[r] : (size_t)(e*CAP + m0 + r);
            cp16(s + adst0 + (uint32_t)i*4096, Aj + ar * Kdim + koff);
        }
#pragma unroll
        for (int i = 0; i < 4; i++)
            cp16(s + bdst0 + (uint32_t)i*4096, Bj + (koff + (size_t)(rB + 16*i)) * outN);
    };

    issue(0, 0); cp_commit();
    issue(1, 1); cp_commit();

    // ---- ldmatrix per-lane components ----
    int wm  = (warp & 3) * 32;
    int wn  = (warp >> 2) * 64;
    // A (non-trans): rows = tokens
    int r16 = lane & 15;
    int coff = lane >> 4;
    int sl7  = lane & 7;
    uint32_t aoff0 = (uint32_t)((wm + r16) * 128);
    // B (trans): rows = k.  kl = lane-const k offset, swizzle key = kl&7 = sub
    int sub = lane & 7;
    int mi  = lane >> 3;
    int kl  = ((mi >> 1) << 3) + sub;     // 0..15
    int slotbit = mi & 1;
    uint32_t bsl[4];
#pragma unroll
    for (int p = 0; p < 4; p++) {
        int slot = (wn >> 3) + 2*p + slotbit;
        bsl[p] = (uint32_t)(A_BYTES + kl*256 + ((slot ^ sub) << 4));
    }

    float acc[2][8][4];
#pragma unroll
    for (int mt = 0; mt < 2; mt++)
#pragma unroll
        for (int nt = 0; nt < 8; nt++)
#pragma unroll
            for (int q = 0; q < 4; q++) acc[mt][nt][q] = 0.f;

    for (int it = 0; it < ITERS; ++it) {
        cp_wait<1>();
        __syncthreads();
        if (it + 2 < ITERS) issue((it + 2) % STAGES, it + 2);
        cp_commit();

        uint32_t stg = smbase + (uint32_t)(it % STAGES) * STAGE_BYTES;

#pragma unroll
        for (int ks = 0; ks < BK; ks += 16) {
            const int c0 = (ks >> 3) + coff;
            const uint32_t csw = (uint32_t)((c0 ^ sl7) << 4);
            uint32_t af[2][4], bf[8][2];
#pragma unroll
            for (int mt = 0; mt < 2; mt++)
                ldsm4(af[mt][0], af[mt][1], af[mt][2], af[mt][3],
                      stg + aoff0 + (uint32_t)mt*2048 + csw);
#pragma unroll
            for (int p = 0; p < 4; p++)
                ldsm4t(bf[2*p][0], bf[2*p+1][0], bf[2*p][1], bf[2*p+1][1],
                       stg + bsl[p] + (uint32_t)(ks << 8));
#pragma unroll
            for (int mt = 0; mt < 2; mt++)
#pragma unroll
                for (int nt = 0; nt < 8; nt++) {
                    asm volatile(
                        "mma.sync.aligned.m16n8k16.row.col.f32.f16.f16.f32 "
                        "{%0,%1,%2,%3}, {%4,%5,%6,%7}, {%8,%9}, {%0,%1,%2,%3};"
                        : "+f"(acc[mt][nt][0]), "+f"(acc[mt][nt][1]),
                          "+f"(acc[mt][nt][2]), "+f"(acc[mt][nt][3])
                        : "r"(af[mt][0]), "r"(af[mt][1]), "r"(af[mt][2]), "r"(af[mt][3]),
                          "r"(bf[nt][0]), "r"(bf[nt][1]));
                }
        }
    }

    // ---- epilogue ----
    int q  = lane & 3;
    int gg = lane >> 2;
#pragma unroll
    for (int mt = 0; mt < 2; mt++) {
        int mrow = wm + mt*16 + gg;
        int t0 = arow[mrow], t1 = arow[mrow + 8];
        float w0 = 0.f, w1v = 0.f;
        if (MODE == 2) {
            w0  = (t0 >= 0) ? g_tv[t0] : 0.f;
            w1v = (t1 >= 0) ? g_tv[t1] : 0.f;
        }
#pragma unroll
        for (int nt = 0; nt < 8; nt++) {
            int col  = n0 + wn + nt*8 + 2*q;
            float bc0 = bias[e * outN + col];
            float bc1 = bias[e * outN + col + 1];
            float v00 = acc[mt][nt][0] + bc0;
            float v01 = acc[mt][nt][1] + bc1;
            float v10 = acc[mt][nt][2] + bc0;
            float v11 = acc[mt][nt][3] + bc1;
            if (MODE == 1) {
                size_t o0 = ((size_t)(e * CAP + m0 + mrow)) * outN + col;
                size_t o1 = o0 + (size_t)8 * outN;
                *(uint32_t*)(g_hh + o0) = pack_h2(fmaxf(v00, 0.f), fmaxf(v01, 0.f));
                *(uint32_t*)(g_hh + o1) = pack_h2(fmaxf(v10, 0.f), fmaxf(v11, 0.f));
            } else {
                if (t0 >= 0) {
                    float* p0 = out + (size_t)t0 * CC + col;
                    atomicAdd(p0,     w0 * v00);
                    atomicAdd(p0 + 1, w0 * v01);
                }
                if (t1 >= 0) {
                    float* p1 = out + (size_t)t1 * CC + col;
                    atomicAdd(p1,     w1v * v10);
                    atomicAdd(p1 + 1, w1v * v11);
                }
            }
        }
    }
}

// ---------------- aux loss ----------------
__global__ void aux_k(float* __restrict__ out, int out_size) {
    int lane = threadIdx.x;
    float v = 0.f;
    if (lane < EE)
        v = (g_imp[lane] / (float)NN) * ((float)g_cnt[lane] / (float)(NN * KKK));
#pragma unroll
    for (int off = 16; off; off >>= 1) v += __shfl_xor_sync(0xffffffffu, v, off);
    if (lane == 0) {
        if (out_size > NN * CC)     out[(size_t)NN * CC] = v;
        if (out_size - 1 > NN * CC) out[(size_t)out_size - 1] = v;
    }
}

// ---------------- launch ----------------
extern "C" void kernel_launch(void* const* d_in, const int* in_sizes, int n_in,
                              void* d_out, int out_size) {
    const float* x  = (const float*)d_in[0];
    const float* rw = (const float*)d_in[1];
    const float* rb = (const float*)d_in[2];
    const float* w1 = (const float*)d_in[3];
    const float* b1 = (const float*)d_in[4];
    const float* w2 = (const float*)d_in[5];
    const float* b2 = (const float*)d_in[6];
    float* out = (float*)d_out;

    cudaFuncSetAttribute(gemm_k<1>, cudaFuncAttributeMaxDynamicSharedMemorySize, SMEM_BYTES);
    cudaFuncSetAttribute(gemm_k<2>, cudaFuncAttributeMaxDynamicSharedMemorySize, SMEM_BYTES);

    __half* xh;  cudaGetSymbolAddress((void**)&xh,  g_xh);
    __half* w1h; cudaGetSymbolAddress((void**)&w1h, g_w1h);
    __half* w2h; cudaGetSymbolAddress((void**)&w2h, g_w2h);

    init_k<<<1, 32>>>();
    router_k<<<NN / 8, 256>>>(x, rw, rb);

    {
        int n8 = (int)((size_t)NN * CC / 8);
        cvt_h<<<(n8 + 255) / 256, 256>>>((const float4*)x, (uint4*)xh, n8);
    }
    {
        int n8 = (int)((size_t)EE * CC * HH / 8);
        cvt_h<<<(n8 + 255) / 256, 256>>>((const float4*)w1, (uint4*)w1h, n8);
        cvt_h<<<(n8 + 255) / 256, 256>>>((const float4*)w2, (uint4*)w2h, n8);
    }

    cudaMemsetAsync(d_out, 0, (size_t)out_size * sizeof(float));

    gemm_k<1><<<dim3(HH / BN, CAP / BM, EE), 256, SMEM_BYTES>>>(b1, nullptr);
    gemm_k<2><<<dim3(CC / BN, CAP / BM, EE), 256, SMEM_BYTES>>>(b2, out);
    aux_k<<<1, 32>>>(out, out_size);
}

// round 11
// speedup vs baseline: 1.1323x; 1.0100x over previous
#include <cuda_runtime.h>
#include <cuda_fp16.h>
#include <cstdint>
#include <math.h>

#define BB 4
#define TT 4096
#define CC 1024
#define EE 8
#define KKK 2
#define HH 4096
#define NN (BB*TT)
#define CAP 8192

#define BM 128
#define BN 128
#define BK 64                               // k-depth per stage
#define STAGES 3
#define A_BYTES (BM*128)                    // 128 token-rows x 128B (64 halves)
#define B_BYTES (BK*256)                    // 64 k-rows x 256B (128 halves)
#define STAGE_BYTES (A_BYTES + B_BYTES)     // 32768
#define SMEM_BYTES (STAGES*STAGE_BYTES)     // 98304

// ---------------- device scratch ----------------
__device__ int    g_cnt[EE];
__device__ float  g_imp[EE];
__device__ int    g_rows[EE*CAP];
__device__ int    g_tokrow[NN*KKK];
__device__ float  g_tv[NN*KKK];
__device__ __half g_hh[(size_t)EE*CAP*HH];     // intermediate (fp16)
__device__ __half g_xh[(size_t)NN*CC];         // fp16 x (written by router)
__device__ __half g_w1h[(size_t)EE*CC*HH];     // fp16 w1, native [e][k=C][n=H]
__device__ __half g_w2h[(size_t)EE*HH*CC];     // fp16 w2, native [e][k=H][n=C]

__device__ __forceinline__ uint32_t pack_h2(float lo, float hi) {
    union { __half2 h; uint32_t u; } cv;
    cv.h = __floats2half2_rn(lo, hi);
    return cv.u;
}
__device__ __forceinline__ void cp16(uint32_t dst, const void* src) {
    asm volatile("cp.async.cg.shared.global [%0], [%1], 16;\n" :: "r"(dst), "l"(src));
}
__device__ __forceinline__ void cp_commit() {
    asm volatile("cp.async.commit_group;\n" ::: "memory");
}
template<int N> __device__ __forceinline__ void cp_wait() {
    asm volatile("cp.async.wait_group %0;\n" :: "n"(N) : "memory");
}
__device__ __forceinline__ void ldsm4(uint32_t& r0, uint32_t& r1, uint32_t& r2, uint32_t& r3,
                                      uint32_t addr) {
    asm volatile("ldmatrix.sync.aligned.m8n8.x4.shared.b16 {%0,%1,%2,%3}, [%4];"
        : "=r"(r0), "=r"(r1), "=r"(r2), "=r"(r3) : "r"(addr));
}
__device__ __forceinline__ void ldsm4t(uint32_t& r0, uint32_t& r1, uint32_t& r2, uint32_t& r3,
                                       uint32_t addr) {
    asm volatile("ldmatrix.sync.aligned.m8n8.x4.trans.shared.b16 {%0,%1,%2,%3}, [%4];"
        : "=r"(r0), "=r"(r1), "=r"(r2), "=r"(r3) : "r"(addr));
}

// ---------------- init ----------------
__global__ void init_k() {
    int i = threadIdx.x;
    if (i < EE) { g_cnt[i] = 0; g_imp[i] = 0.f; }
}

// ---------------- fp32 -> fp16 streaming convert (weights) ----------------
__global__ void cvt_h(const float4* __restrict__ src, uint4* __restrict__ dst, int n8) {
    int i = blockIdx.x * blockDim.x + threadIdx.x;
    if (i >= n8) return;
    float4 a = src[2*i], b = src[2*i+1];
    uint4 o;
    o.x = pack_h2(a.x, a.y);
    o.y = pack_h2(a.z, a.w);
    o.z = pack_h2(b.x, b.y);
    o.w = pack_h2(b.z, b.w);
    dst[i] = o;
}

// ---------------- router (also converts x -> fp16 into g_xh) ----------------
__global__ void router_k(const float* __restrict__ x,
                         const float* __restrict__ rw,
                         const float* __restrict__ rb) {
    int gw   = (int)((blockIdx.x * blockDim.x + threadIdx.x) >> 5);
    int lane = threadIdx.x & 31;
    if (gw >= NN) return;
    const float* xr = x + (size_t)gw * CC;
    __half* xh = g_xh + (size_t)gw * CC;

    float acc[EE];
#pragma unroll
    for (int e = 0; e < EE; e++) acc[e] = 0.f;
    for (int c = lane; c < CC; c += 32) {
        float xv = xr[c];
        xh[c] = __float2half_rn(xv);
        const float* w = rw + c * EE;
#pragma unroll
        for (int e = 0; e < EE; e++) acc[e] = fmaf(xv, w[e], acc[e]);
    }
#pragma unroll
    for (int e = 0; e < EE; e++) {
#pragma unroll
        for (int off = 16; off; off >>= 1)
            acc[e] += __shfl_xor_sync(0xffffffffu, acc[e], off);
    }
    if (lane == 0) {
        float p[EE];
        float mx = -1e30f;
#pragma unroll
        for (int e = 0; e < EE; e++) { p[e] = acc[e] + rb[e]; mx = fmaxf(mx, p[e]); }
        float s = 0.f;
#pragma unroll
        for (int e = 0; e < EE; e++) { p[e] = expf(p[e] - mx); s += p[e]; }
        float inv = 1.f / s;
#pragma unroll
        for (int e = 0; e < EE; e++) p[e] *= inv;

        int i0 = 0;
#pragma unroll
        for (int e = 1; e < EE; e++) if (p[e] > p[i0]) i0 = e;
        int i1 = (i0 == 0) ? 1 : 0;
#pragma unroll
        for (int e = 0; e < EE; e++) if (e != i0 && p[e] > p[i1]) i1 = e;

        g_tv[gw*2]   = p[i0];
        g_tv[gw*2+1] = p[i1];
        int es[2] = { i0, i1 };
#pragma unroll
        for (int s2 = 0; s2 < 2; s2++) {
            int e = es[s2];
            int pos = atomicAdd(&g_cnt[e], 1);
            if (pos < CAP) {
                g_rows[e*CAP + pos]  = gw;
                g_tokrow[gw*2 + s2]  = e*CAP + pos;
            } else {
                g_tokrow[gw*2 + s2]  = -1;
            }
        }
#pragma unroll
        for (int e = 0; e < EE; e++) atomicAdd(&g_imp[e], p[e]);
    }
}

// ---------------- grouped GEMM, fp16 m16n8k16, B via ldmatrix.trans ----------
// MODE 1: h = relu(gather(xh) @ w1[e] + b1[e])  -> fp16 (g_hh)
// MODE 2: out[tok] += w_tok * (h @ w2[e] + b2[e])   (atomic combine)
template<int MODE>
__global__ __launch_bounds__(256, 2)
void gemm_k(const float* __restrict__ bias, float* __restrict__ out) {
    constexpr int  Kdim  = (MODE == 1) ? CC : HH;
    constexpr int  outN  = (MODE == 1) ? HH : CC;
    constexpr int  ITERS = Kdim / BK;

    const __half* A = (MODE == 1) ? g_xh : g_hh;
    const __half* W = (MODE == 1) ? g_w1h : g_w2h;

    int e   = blockIdx.z;
    int cnt = min(g_cnt[e], CAP);
    int m0  = blockIdx.y * BM;
    if (m0 >= cnt) return;
    int n0  = blockIdx.x * BN;

    extern __shared__ char smem[];
    __shared__ int arow[BM];

    int tid  = threadIdx.x;
    int lane = tid & 31, warp = tid >> 5;

    if (tid < BM) {
        int idx = m0 + tid;
        if (MODE == 1) arow[tid] = (idx < cnt) ? g_rows[e*CAP + idx] : 0;
        else           arow[tid] = (idx < cnt) ? g_rows[e*CAP + idx] : -1;
    }
    __syncthreads();

    // ---- cp.async descriptors ----
    int j  = tid & 7;
    int rT = tid >> 3;                 // 0..31
    uint32_t adst0 = (uint32_t)(rT*128 + ((j ^ (rT & 7)) << 4));
    const __half* Aj = A + j*8;
    int j2 = tid & 15;
    int rB = tid >> 4;                 // 0..15
    uint32_t bdst0 = (uint32_t)(A_BYTES + rB*256 + ((j2 ^ (rB & 7)) << 4));
    const __half* Bj = W + (size_t)e * Kdim * outN + n0 + j2*8;

    uint32_t smbase = (uint32_t)__cvta_generic_to_shared(smem);

    auto issue = [&](int stage, int it) {
        uint32_t s = smbase + (uint32_t)stage * STAGE_BYTES;
        size_t koff = (size_t)it * BK;
#pragma unroll
        for (int i = 0; i < 4; i++) {
            int r = rT + 32*i;
            size_t ar = (MODE == 1) ? (size_t)arow[r] : (size_t)(e*CAP + m0 + r);
            cp16(s + adst0 + (uint32_t)i*4096, Aj + ar * Kdim + koff);
        }
#pragma unroll
        for (int i = 0; i < 4; i++)
            cp16(s + bdst0 + (uint32_t)i*4096, Bj + (koff + (size_t)(rB + 16*i)) * outN);
    };

    issue(0, 0); cp_commit();
    issue(1, 1); cp_commit();

    // ---- ldmatrix per-lane components ----
    int wm  = (warp & 3) * 32;
    int wn  = (warp >> 2) * 64;
    int r16 = lane & 15;
    int coff = lane >> 4;
    int sl7  = lane & 7;
    uint32_t aoff0 = (uint32_t)((wm + r16) * 128);
    int sub = lane & 7;
    int mi  = lane >> 3;
    int kl  = ((mi >> 1) << 3) + sub;     // 0..15
    int slotbit = mi & 1;
    uint32_t bsl[4];
#pragma unroll
    for (int p = 0; p < 4; p++) {
        int slot = (wn >> 3) + 2*p + slotbit;
        bsl[p] = (uint32_t)(A_BYTES + kl*256 + ((slot ^ sub) << 4));
    }

    float acc[2][8][4];
#pragma unroll
    for (int mt = 0; mt < 2; mt++)
#pragma unroll
        for (int nt = 0; nt < 8; nt++)
#pragma unroll
            for (int q = 0; q < 4; q++) acc[mt][nt][q] = 0.f;

    for (int it = 0; it < ITERS; ++it) {
        cp_wait<1>();
        __syncthreads();
        if (it + 2 < ITERS) issue((it + 2) % STAGES, it + 2);
        cp_commit();

        uint32_t stg = smbase + (uint32_t)(it % STAGES) * STAGE_BYTES;

#pragma unroll
        for (int ks = 0; ks < BK; ks += 16) {
            const int c0 = (ks >> 3) + coff;
            const uint32_t csw = (uint32_t)((c0 ^ sl7) << 4);
            uint32_t af[2][4], bf[8][2];
#pragma unroll
            for (int mt = 0; mt < 2; mt++)
                ldsm4(af[mt][0], af[mt][1], af[mt][2], af[mt][3],
                      stg + aoff0 + (uint32_t)mt*2048 + csw);
#pragma unroll
            for (int p = 0; p < 4; p++)
                ldsm4t(bf[2*p][0], bf[2*p+1][0], bf[2*p][1], bf[2*p+1][1],
                       stg + bsl[p] + (uint32_t)(ks << 8));
#pragma unroll
            for (int mt = 0; mt < 2; mt++)
#pragma unroll
                for (int nt = 0; nt < 8; nt++) {
                    asm volatile(
                        "mma.sync.aligned.m16n8k16.row.col.f32.f16.f16.f32 "
                        "{%0,%1,%2,%3}, {%4,%5,%6,%7}, {%8,%9}, {%0,%1,%2,%3};"
                        : "+f"(acc[mt][nt][0]), "+f"(acc[mt][nt][1]),
                          "+f"(acc[mt][nt][2]), "+f"(acc[mt][nt][3])
                        : "r"(af[mt][0]), "r"(af[mt][1]), "r"(af[mt][2]), "r"(af[mt][3]),
                          "r"(bf[nt][0]), "r"(bf[nt][1]));
                }
        }
    }

    // ---- epilogue ----
    int q  = lane & 3;
    int gg = lane >> 2;
#pragma unroll
    for (int mt = 0; mt < 2; mt++) {
        int mrow = wm + mt*16 + gg;
        int t0 = arow[mrow], t1 = arow[mrow + 8];
        float w0 = 0.f, w1v = 0.f;
        if (MODE == 2) {
            w0  = (t0 >= 0) ? g_tv[t0] : 0.f;
            w1v = (t1 >= 0) ? g_tv[t1] : 0.f;
        }
#pragma unroll
        for (int nt = 0; nt < 8; nt++) {
            int col  = n0 + wn + nt*8 + 2*q;
            float bc0 = bias[e * outN + col];
            float bc1 = bias[e * outN + col + 1];
            float v00 = acc[mt][nt][0] + bc0;
            float v01 = acc[mt][nt][1] + bc1;
            float v10 = acc[mt][nt][2] + bc0;
            float v11 = acc[mt][nt][3] + bc1;
            if (MODE == 1) {
                size_t o0 = ((size_t)(e * CAP + m0 + mrow)) * outN + col;
                size_t o1 = o0 + (size_t)8 * outN;
                *(uint32_t*)(g_hh + o0) = pack_h2(fmaxf(v00, 0.f), fmaxf(v01, 0.f));
                *(uint32_t*)(g_hh + o1) = pack_h2(fmaxf(v10, 0.f), fmaxf(v11, 0.f));
            } else {
                if (t0 >= 0) {
                    float* p0 = out + (size_t)t0 * CC + col;
                    atomicAdd(p0,     w0 * v00);
                    atomicAdd(p0 + 1, w0 * v01);
                }
                if (t1 >= 0) {
                    float* p1 = out + (size_t)t1 * CC + col;
                    atomicAdd(p1,     w1v * v10);
                    atomicAdd(p1 + 1, w1v * v11);
                }
            }
        }
    }
}

// ---------------- aux loss ----------------
__global__ void aux_k(float* __restrict__ out, int out_size) {
    int lane = threadIdx.x;
    float v = 0.f;
    if (lane < EE)
        v = (g_imp[lane] / (float)NN) * ((float)g_cnt[lane] / (float)(NN * KKK));
#pragma unroll
    for (int off = 16; off; off >>= 1) v += __shfl_xor_sync(0xffffffffu, v, off);
    if (lane == 0) {
        if (out_size > NN * CC)     out[(size_t)NN * CC] = v;
        if (out_size - 1 > NN * CC) out[(size_t)out_size - 1] = v;
    }
}

// ---------------- launch ----------------
extern "C" void kernel_launch(void* const* d_in, const int* in_sizes, int n_in,
                              void* d_out, int out_size) {
    const float* x  = (const float*)d_in[0];
    const float* rw = (const float*)d_in[1];
    const float* rb = (const float*)d_in[2];
    const float* w1 = (const float*)d_in[3];
    const float* b1 = (const float*)d_in[4];
    const float* w2 = (const float*)d_in[5];
    const float* b2 = (const float*)d_in[6];
    float* out = (float*)d_out;

    static cudaStream_t s2 = nullptr;
    static cudaEvent_t evStart = nullptr, evW1 = nullptr, evW2 = nullptr;
    if (!s2) {
        cudaStreamCreateWithFlags(&s2, cudaStreamNonBlocking);
        cudaEventCreateWithFlags(&evStart, cudaEventDisableTiming);
        cudaEventCreateWithFlags(&evW1,   cudaEventDisableTiming);
        cudaEventCreateWithFlags(&evW2,   cudaEventDisableTiming);
    }

    cudaFuncSetAttribute(gemm_k<1>, cudaFuncAttributeMaxDynamicSharedMemorySize, SMEM_BYTES);
    cudaFuncSetAttribute(gemm_k<2>, cudaFuncAttributeMaxDynamicSharedMemorySize, SMEM_BYTES);

    __half* w1h; cudaGetSymbolAddress((void**)&w1h, g_w1h);
    __half* w2h; cudaGetSymbolAddress((void**)&w2h, g_w2h);

    // fork s2 off the (captured) main stream
    cudaEventRecord(evStart, 0);
    cudaStreamWaitEvent(s2, evStart, 0);

    // s2: weight conversions
    {
        int n8 = (int)((size_t)EE * CC * HH / 8);
        cvt_h<<<(n8 + 255) / 256, 256, 0, s2>>>((const float4*)w1, (uint4*)w1h, n8);
        cudaEventRecord(evW1, s2);
        cvt_h<<<(n8 + 255) / 256, 256, 0, s2>>>((const float4*)w2, (uint4*)w2h, n8);
        cudaEventRecord(evW2, s2);
    }

    // main: router (+x->fp16) and output zeroing
    init_k<<<1, 32>>>();
    router_k<<<NN / 8, 256>>>(x, rw, rb);
    cudaMemsetAsync(d_out, 0, (size_t)out_size * sizeof(float));

    // gemm1 needs router + w1h
    cudaStreamWaitEvent(0, evW1, 0);
    gemm_k<1><<<dim3(HH / BN, CAP / BM, EE), 256, SMEM_BYTES>>>(b1, nullptr);
    // gemm2 additionally needs w2h
    cudaStreamWaitEvent(0, evW2, 0);
    gemm_k<2><<<dim3(CC / BN, CAP / BM, EE), 256, SMEM_BYTES>>>(b2, out);
    aux_k<<<1, 32>>>(out, out_size);
}

// round 12
// speedup vs baseline: 1.1363x; 1.0036x over previous
#include <cuda_runtime.h>
#include <cuda_fp16.h>
#include <cstdint>
#include <math.h>

#define BB 4
#define TT 4096
#define CC 1024
#define EE 8
#define KKK 2
#define HH 4096
#define NN (BB*TT)
#define CAP 8192

#define BM 128
#define BN 128
#define BK 64                               // k-depth per stage
#define STAGES 3
#define A_BYTES (BM*128)                    // 128 token-rows x 128B (64 halves)
#define B_BYTES (BK*256)                    // 64 k-rows x 256B (128 halves)
#define STAGE_BYTES (A_BYTES + B_BYTES)     // 32768
#define SMEM_BYTES (STAGES*STAGE_BYTES)     // 98304

// ---------------- device scratch ----------------
__device__ int    g_cnt[EE];
__device__ float  g_imp[EE];
__device__ int    g_rows[EE*CAP];
__device__ int    g_tokrow[NN*KKK];
__device__ float  g_tv[NN*KKK];
__device__ __half g_hh[(size_t)EE*CAP*HH];     // intermediate (fp16)
__device__ __half g_xh[(size_t)NN*CC];         // fp16 x (written by router)
__device__ __half g_w1h[(size_t)EE*CC*HH];     // fp16 w1, native [e][k=C][n=H]
__device__ __half g_w2h[(size_t)EE*HH*CC];     // fp16 w2, native [e][k=H][n=C]

__device__ __forceinline__ uint32_t pack_h2(float lo, float hi) {
    union { __half2 h; uint32_t u; } cv;
    cv.h = __floats2half2_rn(lo, hi);
    return cv.u;
}
__device__ __forceinline__ void cp16(uint32_t dst, const void* src) {
    asm volatile("cp.async.cg.shared.global [%0], [%1], 16;\n" :: "r"(dst), "l"(src));
}
__device__ __forceinline__ void cp_commit() {
    asm volatile("cp.async.commit_group;\n" ::: "memory");
}
template<int N> __device__ __forceinline__ void cp_wait() {
    asm volatile("cp.async.wait_group %0;\n" :: "n"(N) : "memory");
}
__device__ __forceinline__ void ldsm4(uint32_t& r0, uint32_t& r1, uint32_t& r2, uint32_t& r3,
                                      uint32_t addr) {
    asm volatile("ldmatrix.sync.aligned.m8n8.x4.shared.b16 {%0,%1,%2,%3}, [%4];"
        : "=r"(r0), "=r"(r1), "=r"(r2), "=r"(r3) : "r"(addr));
}
__device__ __forceinline__ void ldsm4t(uint32_t& r0, uint32_t& r1, uint32_t& r2, uint32_t& r3,
                                       uint32_t addr) {
    asm volatile("ldmatrix.sync.aligned.m8n8.x4.trans.shared.b16 {%0,%1,%2,%3}, [%4];"
        : "=r"(r0), "=r"(r1), "=r"(r2), "=r"(r3) : "r"(addr));
}

// ---------------- init ----------------
__global__ void init_k() {
    int i = threadIdx.x;
    if (i < EE) { g_cnt[i] = 0; g_imp[i] = 0.f; }
}

// ---------------- fp32 -> fp16 streaming convert (weights) ----------------
__global__ void cvt_h(const float4* __restrict__ src, uint4* __restrict__ dst, int n8) {
    int i = blockIdx.x * blockDim.x + threadIdx.x;
    if (i >= n8) return;
    float4 a = src[2*i], b = src[2*i+1];
    uint4 o;
    o.x = pack_h2(a.x, a.y);
    o.y = pack_h2(a.z, a.w);
    o.z = pack_h2(b.x, b.y);
    o.w = pack_h2(b.z, b.w);
    dst[i] = o;
}

// ---------------- router (vectorized; also converts x -> fp16) ----------------
__global__ void router_k(const float* __restrict__ x,
                         const float* __restrict__ rw,
                         const float* __restrict__ rb) {
    int gw   = (int)((blockIdx.x * blockDim.x + threadIdx.x) >> 5);
    int lane = threadIdx.x & 31;
    if (gw >= NN) return;
    const float4* xr4 = (const float4*)(x + (size_t)gw * CC);
    uint2* xh2 = (uint2*)(g_xh + (size_t)gw * CC);
    const float4* rw4 = (const float4*)rw;

    float acc[EE];
#pragma unroll
    for (int e = 0; e < EE; e++) acc[e] = 0.f;

#pragma unroll 2
    for (int i = 0; i < CC/128; i++) {          // 8 iterations
        int c4 = i*32 + lane;                   // float4 index; c = 4*c4
        float4 v = xr4[c4];
        uint2 o;
        o.x = pack_h2(v.x, v.y);
        o.y = pack_h2(v.z, v.w);
        xh2[c4] = o;
        // rw rows 4*c4 .. 4*c4+3, each EE=8 floats = 2 float4
        const float4* wr = rw4 + (size_t)c4 * 8;
#pragma unroll
        for (int r = 0; r < 4; r++) {
            float xv = (&v.x)[r];
            float4 wa = wr[2*r], wb = wr[2*r + 1];
            acc[0] = fmaf(xv, wa.x, acc[0]);
            acc[1] = fmaf(xv, wa.y, acc[1]);
            acc[2] = fmaf(xv, wa.z, acc[2]);
            acc[3] = fmaf(xv, wa.w, acc[3]);
            acc[4] = fmaf(xv, wb.x, acc[4]);
            acc[5] = fmaf(xv, wb.y, acc[5]);
            acc[6] = fmaf(xv, wb.z, acc[6]);
            acc[7] = fmaf(xv, wb.w, acc[7]);
        }
    }
#pragma unroll
    for (int e = 0; e < EE; e++) {
#pragma unroll
        for (int off = 16; off; off >>= 1)
            acc[e] += __shfl_xor_sync(0xffffffffu, acc[e], off);
    }
    if (lane == 0) {
        float p[EE];
        float mx = -1e30f;
#pragma unroll
        for (int e = 0; e < EE; e++) { p[e] = acc[e] + rb[e]; mx = fmaxf(mx, p[e]); }
        float s = 0.f;
#pragma unroll
        for (int e = 0; e < EE; e++) { p[e] = expf(p[e] - mx); s += p[e]; }
        float inv = 1.f / s;
#pragma unroll
        for (int e = 0; e < EE; e++) p[e] *= inv;

        int i0 = 0;
#pragma unroll
        for (int e = 1; e < EE; e++) if (p[e] > p[i0]) i0 = e;
        int i1 = (i0 == 0) ? 1 : 0;
#pragma unroll
        for (int e = 0; e < EE; e++) if (e != i0 && p[e] > p[i1]) i1 = e;

        g_tv[gw*2]   = p[i0];
        g_tv[gw*2+1] = p[i1];
        int es[2] = { i0, i1 };
#pragma unroll
        for (int s2 = 0; s2 < 2; s2++) {
            int e = es[s2];
            int pos = atomicAdd(&g_cnt[e], 1);
            if (pos < CAP) {
                g_rows[e*CAP + pos]  = gw;
                g_tokrow[gw*2 + s2]  = e*CAP + pos;
            } else {
                g_tokrow[gw*2 + s2]  = -1;
            }
        }
#pragma unroll
        for (int e = 0; e < EE; e++) atomicAdd(&g_imp[e], p[e]);
    }
}

// ---------------- grouped GEMM, fp16 m16n8k16, B via ldmatrix.trans ----------
// MODE 1: h = relu(gather(xh) @ w1[e] + b1[e])  -> fp16 (g_hh)
// MODE 2: out[tok] += w_tok * (h @ w2[e] + b2[e])   (atomic combine)
template<int MODE>
__global__ __launch_bounds__(256, 2)
void gemm_k(const float* __restrict__ bias, float* __restrict__ out) {
    constexpr int  Kdim  = (MODE == 1) ? CC : HH;
    constexpr int  outN  = (MODE == 1) ? HH : CC;
    constexpr int  ITERS = Kdim / BK;

    const __half* A = (MODE == 1) ? g_xh : g_hh;
    const __half* W = (MODE == 1) ? g_w1h : g_w2h;

    int e   = blockIdx.z;
    int cnt = min(g_cnt[e], CAP);
    int m0  = blockIdx.y * BM;
    if (m0 >= cnt) return;
    int n0  = blockIdx.x * BN;

    extern __shared__ char smem[];
    __shared__ int arow[BM];

    int tid  = threadIdx.x;
    int lane = tid & 31, warp = tid >> 5;

    if (tid < BM) {
        int idx = m0 + tid;
        if (MODE == 1) arow[tid] = (idx < cnt) ? g_rows[e*CAP + idx] : 0;
        else           arow[tid] = (idx < cnt) ? g_rows[e*CAP + idx] : -1;
    }
    __syncthreads();

    // ---- cp.async descriptors ----
    int j  = tid & 7;
    int rT = tid >> 3;                 // 0..31
    uint32_t adst0 = (uint32_t)(rT*128 + ((j ^ (rT & 7)) << 4));
    const __half* Aj = A + j*8;
    int j2 = tid & 15;
    int rB = tid >> 4;                 // 0..15
    uint32_t bdst0 = (uint32_t)(A_BYTES + rB*256 + ((j2 ^ (rB & 7)) << 4));
    const __half* Bj = W + (size_t)e * Kdim * outN + n0 + j2*8;

    uint32_t smbase = (uint32_t)__cvta_generic_to_shared(smem);

    auto issue = [&](int stage, int it) {
        uint32_t s = smbase + (uint32_t)stage * STAGE_BYTES;
        size_t koff = (size_t)it * BK;
#pragma unroll
        for (int i = 0; i < 4; i++) {
            int r = rT + 32*i;
            size_t ar = (MODE == 1) ? (size_t)arow[r] : (size_t)(e*CAP + m0 + r);
            cp16(s + adst0 + (uint32_t)i*4096, Aj + ar * Kdim + koff);
        }
#pragma unroll
        for (int i = 0; i < 4; i++)
            cp16(s + bdst0 + (uint32_t)i*4096, Bj + (koff + (size_t)(rB + 16*i)) * outN);
    };

    issue(0, 0); cp_commit();
    issue(1, 1); cp_commit();

    // ---- ldmatrix per-lane components ----
    int wm  = (warp & 3) * 32;
    int wn  = (warp >> 2) * 64;
    int r16 = lane & 15;
    int coff = lane >> 4;
    int sl7  = lane & 7;
    uint32_t aoff0 = (uint32_t)((wm + r16) * 128);
    int sub = lane & 7;
    int mi  = lane >> 3;
    int kl  = ((mi >> 1) << 3) + sub;     // 0..15
    int slotbit = mi & 1;
    uint32_t bsl[4];
#pragma unroll
    for (int p = 0; p < 4; p++) {
        int slot = (wn >> 3) + 2*p + slotbit;
        bsl[p] = (uint32_t)(A_BYTES + kl*256 + ((slot ^ sub) << 4));
    }

    float acc[2][8][4];
#pragma unroll
    for (int mt = 0; mt < 2; mt++)
#pragma unroll
        for (int nt = 0; nt < 8; nt++)
#pragma unroll
            for (int q = 0; q < 4; q++) acc[mt][nt][q] = 0.f;

    for (int it = 0; it < ITERS; ++it) {
        cp_wait<1>();
        __syncthreads();
        if (it + 2 < ITERS) issue((it + 2) % STAGES, it + 2);
        cp_commit();

        uint32_t stg = smbase + (uint32_t)(it % STAGES) * STAGE_BYTES;

#pragma unroll
        for (int ks = 0; ks < BK; ks += 16) {
            const int c0 = (ks >> 3) + coff;
            const uint32_t csw = (uint32_t)((c0 ^ sl7) << 4);
            uint32_t af[2][4], bf[8][2];
#pragma unroll
            for (int mt = 0; mt < 2; mt++)
                ldsm4(af[mt][0], af[mt][1], af[mt][2], af[mt][3],
                      stg + aoff0 + (uint32_t)mt*2048 + csw);
#pragma unroll
            for (int p = 0; p < 4; p++)
                ldsm4t(bf[2*p][0], bf[2*p+1][0], bf[2*p][1], bf[2*p+1][1],
                       stg + bsl[p] + (uint32_t)(ks << 8));
#pragma unroll
            for (int mt = 0; mt < 2; mt++)
#pragma unroll
                for (int nt = 0; nt < 8; nt++) {
                    asm volatile(
                        "mma.sync.aligned.m16n8k16.row.col.f32.f16.f16.f32 "
                        "{%0,%1,%2,%3}, {%4,%5,%6,%7}, {%8,%9}, {%0,%1,%2,%3};"
                        : "+f"(acc[mt][nt][0]), "+f"(acc[mt][nt][1]),
                          "+f"(acc[mt][nt][2]), "+f"(acc[mt][nt][3])
                        : "r"(af[mt][0]), "r"(af[mt][1]), "r"(af[mt][2]), "r"(af[mt][3]),
                          "r"(bf[nt][0]), "r"(bf[nt][1]));
                }
        }
    }

    // ---- epilogue ----
    int q  = lane & 3;
    int gg = lane >> 2;
#pragma unroll
    for (int mt = 0; mt < 2; mt++) {
        int mrow = wm + mt*16 + gg;
        int t0 = arow[mrow], t1 = arow[mrow + 8];
        float w0 = 0.f, w1v = 0.f;
        if (MODE == 2) {
            w0  = (t0 >= 0) ? g_tv[t0] : 0.f;
            w1v = (t1 >= 0) ? g_tv[t1] : 0.f;
        }
#pragma unroll
        for (int nt = 0; nt < 8; nt++) {
            int col  = n0 + wn + nt*8 + 2*q;
            float bc0 = bias[e * outN + col];
            float bc1 = bias[e * outN + col + 1];
            float v00 = acc[mt][nt][0] + bc0;
            float v01 = acc[mt][nt][1] + bc1;
            float v10 = acc[mt][nt][2] + bc0;
            float v11 = acc[mt][nt][3] + bc1;
            if (MODE == 1) {
                size_t o0 = ((size_t)(e * CAP + m0 + mrow)) * outN + col;
                size_t o1 = o0 + (size_t)8 * outN;
                *(uint32_t*)(g_hh + o0) = pack_h2(fmaxf(v00, 0.f), fmaxf(v01, 0.f));
                *(uint32_t*)(g_hh + o1) = pack_h2(fmaxf(v10, 0.f), fmaxf(v11, 0.f));
            } else {
                if (t0 >= 0) {
                    float* p0 = out + (size_t)t0 * CC + col;
                    atomicAdd(p0,     w0 * v00);
                    atomicAdd(p0 + 1, w0 * v01);
                }
                if (t1 >= 0) {
                    float* p1 = out + (size_t)t1 * CC + col;
                    atomicAdd(p1,     w1v * v10);
                    atomicAdd(p1 + 1, w1v * v11);
                }
            }
        }
    }
}

// ---------------- aux loss ----------------
__global__ void aux_k(float* __restrict__ out, int out_size) {
    int lane = threadIdx.x;
    float v = 0.f;
    if (lane < EE)
        v = (g_imp[lane] / (float)NN) * ((float)g_cnt[lane] / (float)(NN * KKK));
#pragma unroll
    for (int off = 16; off; off >>= 1) v += __shfl_xor_sync(0xffffffffu, v, off);
    if (lane == 0) {
        if (out_size > NN * CC)     out[(size_t)NN * CC] = v;
        if (out_size - 1 > NN * CC) out[(size_t)out_size - 1] = v;
    }
}

// ---------------- launch ----------------
extern "C" void kernel_launch(void* const* d_in, const int* in_sizes, int n_in,
                              void* d_out, int out_size) {
    const float* x  = (const float*)d_in[0];
    const float* rw = (const float*)d_in[1];
    const float* rb = (const float*)d_in[2];
    const float* w1 = (const float*)d_in[3];
    const float* b1 = (const float*)d_in[4];
    const float* w2 = (const float*)d_in[5];
    const float* b2 = (const float*)d_in[6];
    float* out = (float*)d_out;

    static cudaStream_t s2 = nullptr;
    static cudaEvent_t evStart = nullptr, evW1 = nullptr, evW2 = nullptr;
    if (!s2) {
        cudaStreamCreateWithFlags(&s2, cudaStreamNonBlocking);
        cudaEventCreateWithFlags(&evStart, cudaEventDisableTiming);
        cudaEventCreateWithFlags(&evW1,   cudaEventDisableTiming);
        cudaEventCreateWithFlags(&evW2,   cudaEventDisableTiming);
    }

    cudaFuncSetAttribute(gemm_k<1>, cudaFuncAttributeMaxDynamicSharedMemorySize, SMEM_BYTES);
    cudaFuncSetAttribute(gemm_k<2>, cudaFuncAttributeMaxDynamicSharedMemorySize, SMEM_BYTES);

    __half* w1h; cudaGetSymbolAddress((void**)&w1h, g_w1h);
    __half* w2h; cudaGetSymbolAddress((void**)&w2h, g_w2h);

    // fork s2 off the (captured) main stream
    cudaEventRecord(evStart, 0);
    cudaStreamWaitEvent(s2, evStart, 0);

    // s2: weight conversions
    {
        int n8 = (int)((size_t)EE * CC * HH / 8);
        cvt_h<<<(n8 + 255) / 256, 256, 0, s2>>>((const float4*)w1, (uint4*)w1h, n8);
        cudaEventRecord(evW1, s2);
        cvt_h<<<(n8 + 255) / 256, 256, 0, s2>>>((const float4*)w2, (uint4*)w2h, n8);
        cudaEventRecord(evW2, s2);
    }

    // main: router (+x->fp16) and output zeroing
    init_k<<<1, 32>>>();
    router_k<<<NN / 8, 256>>>(x, rw, rb);
    cudaMemsetAsync(d_out, 0, (size_t)out_size * sizeof(float));

    // gemm1 needs router + w1h
    cudaStreamWaitEvent(0, evW1, 0);
    gemm_k<1><<<dim3(HH / BN, CAP / BM, EE), 256, SMEM_BYTES>>>(b1, nullptr);
    // gemm2 additionally needs w2h
    cudaStreamWaitEvent(0, evW2, 0);
    gemm_k<2><<<dim3(CC / BN, CAP / BM, EE), 256, SMEM_BYTES>>>(b2, out);
    aux_k<<<1, 32>>>(out, out_size);
}

// round 13
// speedup vs baseline: 1.2072x; 1.0624x over previous
#include <cuda_runtime.h>
#include <cuda_fp16.h>
#include <cstdint>
#include <math.h>

#define BB 4
#define TT 4096
#define CC 1024
#define EE 8
#define KKK 2
#define HH 4096
#define NN (BB*TT)
#define CAP 8192

#define BM 128
#define BN 128
#define BK 64                               // k-depth per stage
#define STAGES 3
#define A_BYTES (BM*128)                    // 128 token-rows x 128B (64 halves)
#define B_BYTES (BK*256)                    // 64 k-rows x 256B (128 halves)
#define STAGE_BYTES (A_BYTES + B_BYTES)     // 32768
#define SMEM_BYTES (STAGES*STAGE_BYTES)     // 98304

// ---------------- device scratch ----------------
__device__ int    g_cnt[EE];
__device__ float  g_imp[EE];
__device__ int    g_rows[EE*CAP];
__device__ int    g_tokrow[NN*KKK];
__device__ float  g_tv[NN*KKK];
__device__ __half g_hh[(size_t)EE*CAP*HH];     // intermediate (fp16)
__device__ __half g_xh[(size_t)NN*CC];         // fp16 x (written by router)
__device__ __half g_w1h[(size_t)EE*CC*HH];     // fp16 w1, native [e][k=C][n=H]
__device__ __half g_w2h[(size_t)EE*HH*CC];     // fp16 w2, native [e][k=H][n=C]

__device__ __forceinline__ uint32_t pack_h2(float lo, float hi) {
    union { __half2 h; uint32_t u; } cv;
    cv.h = __floats2half2_rn(lo, hi);
    return cv.u;
}
__device__ __forceinline__ void cp16(uint32_t dst, const void* src) {
    asm volatile("cp.async.cg.shared.global [%0], [%1], 16;\n" :: "r"(dst), "l"(src));
}
__device__ __forceinline__ void cp_commit() {
    asm volatile("cp.async.commit_group;\n" ::: "memory");
}
template<int N> __device__ __forceinline__ void cp_wait() {
    asm volatile("cp.async.wait_group %0;\n" :: "n"(N) : "memory");
}
__device__ __forceinline__ void ldsm4(uint32_t& r0, uint32_t& r1, uint32_t& r2, uint32_t& r3,
                                      uint32_t addr) {
    asm volatile("ldmatrix.sync.aligned.m8n8.x4.shared.b16 {%0,%1,%2,%3}, [%4];"
        : "=r"(r0), "=r"(r1), "=r"(r2), "=r"(r3) : "r"(addr));
}
__device__ __forceinline__ void ldsm4t(uint32_t& r0, uint32_t& r1, uint32_t& r2, uint32_t& r3,
                                       uint32_t addr) {
    asm volatile("ldmatrix.sync.aligned.m8n8.x4.trans.shared.b16 {%0,%1,%2,%3}, [%4];"
        : "=r"(r0), "=r"(r1), "=r"(r2), "=r"(r3) : "r"(addr));
}

// ---------------- init ----------------
__global__ void init_k() {
    int i = threadIdx.x;
    if (i < EE) { g_cnt[i] = 0; g_imp[i] = 0.f; }
}

// ---------------- fp32 -> fp16 streaming convert (weights) ----------------
__global__ void cvt_h(const float4* __restrict__ src, uint4* __restrict__ dst, int n8) {
    int i = blockIdx.x * blockDim.x + threadIdx.x;
    if (i >= n8) return;
    float4 a = src[2*i], b = src[2*i+1];
    uint4 o;
    o.x = pack_h2(a.x, a.y);
    o.y = pack_h2(a.z, a.w);
    o.z = pack_h2(b.x, b.y);
    o.w = pack_h2(b.z, b.w);
    dst[i] = o;
}

// ---------------- router (block-aggregated atomics; x -> fp16 fused) --------
__global__ void router_k(const float* __restrict__ x,
                         const float* __restrict__ rw,
                         const float* __restrict__ rb) {
    __shared__ float simp[EE];
    __shared__ int   scnt[EE];
    __shared__ int   sbase[EE];
    __shared__ int   tok_e[8][2];
    __shared__ int   tok_lp[8][2];

    int tid  = threadIdx.x;
    int w    = tid >> 5;
    int lane = tid & 31;
    int gw   = blockIdx.x * 8 + w;

    if (tid < EE) { simp[tid] = 0.f; scnt[tid] = 0; }
    __syncthreads();

    const float4* xr4 = (const float4*)(x + (size_t)gw * CC);
    uint2* xh2 = (uint2*)(g_xh + (size_t)gw * CC);
    const float4* rw4 = (const float4*)rw;

    float acc[EE];
#pragma unroll
    for (int e = 0; e < EE; e++) acc[e] = 0.f;

#pragma unroll 2
    for (int i = 0; i < CC/128; i++) {          // 8 iterations
        int c4 = i*32 + lane;
        float4 v = xr4[c4];
        uint2 o;
        o.x = pack_h2(v.x, v.y);
        o.y = pack_h2(v.z, v.w);
        xh2[c4] = o;
        const float4* wr = rw4 + (size_t)c4 * 8;
#pragma unroll
        for (int r = 0; r < 4; r++) {
            float xv = (&v.x)[r];
            float4 wa = wr[2*r], wb = wr[2*r + 1];
            acc[0] = fmaf(xv, wa.x, acc[0]);
            acc[1] = fmaf(xv, wa.y, acc[1]);
            acc[2] = fmaf(xv, wa.z, acc[2]);
            acc[3] = fmaf(xv, wa.w, acc[3]);
            acc[4] = fmaf(xv, wb.x, acc[4]);
            acc[5] = fmaf(xv, wb.y, acc[5]);
            acc[6] = fmaf(xv, wb.z, acc[6]);
            acc[7] = fmaf(xv, wb.w, acc[7]);
        }
    }
#pragma unroll
    for (int e = 0; e < EE; e++) {
#pragma unroll
        for (int off = 16; off; off >>= 1)
            acc[e] += __shfl_xor_sync(0xffffffffu, acc[e], off);
    }
    if (lane == 0) {
        float p[EE];
        float mx = -1e30f;
#pragma unroll
        for (int e = 0; e < EE; e++) { p[e] = acc[e] + rb[e]; mx = fmaxf(mx, p[e]); }
        float s = 0.f;
#pragma unroll
        for (int e = 0; e < EE; e++) { p[e] = expf(p[e] - mx); s += p[e]; }
        float inv = 1.f / s;
#pragma unroll
        for (int e = 0; e < EE; e++) p[e] *= inv;

        int i0 = 0;
#pragma unroll
        for (int e = 1; e < EE; e++) if (p[e] > p[i0]) i0 = e;
        int i1 = (i0 == 0) ? 1 : 0;
#pragma unroll
        for (int e = 0; e < EE; e++) if (e != i0 && p[e] > p[i1]) i1 = e;

        g_tv[gw*2]   = p[i0];
        g_tv[gw*2+1] = p[i1];
        int es[2] = { i0, i1 };
#pragma unroll
        for (int s2 = 0; s2 < 2; s2++) {
            int e = es[s2];
            tok_e[w][s2]  = e;
            tok_lp[w][s2] = atomicAdd(&scnt[e], 1);
        }
#pragma unroll
        for (int e = 0; e < EE; e++) atomicAdd(&simp[e], p[e]);
    }
    __syncthreads();
    if (tid < EE) {
        sbase[tid] = atomicAdd(&g_cnt[tid], scnt[tid]);
        atomicAdd(&g_imp[tid], simp[tid]);
    }
    __syncthreads();
    if (tid < 16) {
        int wt = tid >> 1, s2 = tid & 1;
        int e   = tok_e[wt][s2];
        int pos = sbase[e] + tok_lp[wt][s2];
        int gt  = blockIdx.x * 8 + wt;
        if (pos < CAP) {
            g_rows[e*CAP + pos]  = gt;
            g_tokrow[gt*2 + s2]  = e*CAP + pos;
        } else {
            g_tokrow[gt*2 + s2]  = -1;
        }
    }
}

// ---------------- grouped GEMM, fp16 m16n8k16, B via ldmatrix.trans ----------
// MODE 1: h = relu(gather(xh) @ w1[e] + b1[e])  -> fp16 (g_hh)
// MODE 2: out[tok] += w_tok * (h @ w2[e] + b2[e])   (atomic combine)
template<int MODE>
__global__ __launch_bounds__(256, 2)
void gemm_k(const float* __restrict__ bias, float* __restrict__ out) {
    constexpr int  Kdim  = (MODE == 1) ? CC : HH;
    constexpr int  outN  = (MODE == 1) ? HH : CC;
    constexpr int  ITERS = Kdim / BK;

    const __half* A = (MODE == 1) ? g_xh : g_hh;
    const __half* W = (MODE == 1) ? g_w1h : g_w2h;

    int e   = blockIdx.z;
    int cnt = min(g_cnt[e], CAP);
    int m0  = blockIdx.y * BM;
    if (m0 >= cnt) return;
    int n0  = blockIdx.x * BN;

    extern __shared__ char smem[];
    __shared__ int arow[BM];

    int tid  = threadIdx.x;
    int lane = tid & 31, warp = tid >> 5;

    if (tid < BM) {
        int idx = m0 + tid;
        if (MODE == 1) arow[tid] = (idx < cnt) ? g_rows[e*CAP + idx] : 0;
        else           arow[tid] = (idx < cnt) ? g_rows[e*CAP + idx] : -1;
    }
    __syncthreads();

    // ---- cp.async descriptors ----
    int j  = tid & 7;
    int rT = tid >> 3;                 // 0..31
    uint32_t adst0 = (uint32_t)(rT*128 + ((j ^ (rT & 7)) << 4));
    const __half* Aj = A + j*8;
    int j2 = tid & 15;
    int rB = tid >> 4;                 // 0..15
    uint32_t bdst0 = (uint32_t)(A_BYTES + rB*256 + ((j2 ^ (rB & 7)) << 4));
    const __half* Bj = W + (size_t)e * Kdim * outN + n0 + j2*8;

    uint32_t smbase = (uint32_t)__cvta_generic_to_shared(smem);

    auto issue = [&](int stage, int it) {
        uint32_t s = smbase + (uint32_t)stage * STAGE_BYTES;
        size_t koff = (size_t)it * BK;
#pragma unroll
        for (int i = 0; i < 4; i++) {
            int r = rT + 32*i;
            size_t ar = (MODE == 1) ? (size_t)arow[r] : (size_t)(e*CAP + m0 + r);
            cp16(s + adst0 + (uint32_t)i*4096, Aj + ar * Kdim + koff);
        }
#pragma unroll
        for (int i = 0; i < 4; i++)
            cp16(s + bdst0 + (uint32_t)i*4096, Bj + (koff + (size_t)(rB + 16*i)) * outN);
    };

    issue(0, 0); cp_commit();
    issue(1, 1); cp_commit();

    // ---- ldmatrix per-lane components ----
    int wm  = (warp & 3) * 32;
    int wn  = (warp >> 2) * 64;
    int r16 = lane & 15;
    int coff = lane >> 4;
    int sl7  = lane & 7;
    uint32_t aoff0 = (uint32_t)((wm + r16) * 128);
    int sub = lane & 7;
    int mi  = lane >> 3;
    int kl  = ((mi >> 1) << 3) + sub;     // 0..15
    int slotbit = mi & 1;
    uint32_t bsl[4];
#pragma unroll
    for (int p = 0; p < 4; p++) {
        int slot = (wn >> 3) + 2*p + slotbit;
        bsl[p] = (uint32_t)(A_BYTES + kl*256 + ((slot ^ sub) << 4));
    }

    float acc[2][8][4];
#pragma unroll
    for (int mt = 0; mt < 2; mt++)
#pragma unroll
        for (int nt = 0; nt < 8; nt++)
#pragma unroll
            for (int q = 0; q < 4; q++) acc[mt][nt][q] = 0.f;

    for (int it = 0; it < ITERS; ++it) {
        cp_wait<1>();
        __syncthreads();
        if (it + 2 < ITERS) issue((it + 2) % STAGES, it + 2);
        cp_commit();

        uint32_t stg = smbase + (uint32_t)(it % STAGES) * STAGE_BYTES;

#pragma unroll
        for (int ks = 0; ks < BK; ks += 16) {
            const int c0 = (ks >> 3) + coff;
            const uint32_t csw = (uint32_t)((c0 ^ sl7) << 4);
            uint32_t af[2][4], bf[8][2];
#pragma unroll
            for (int mt = 0; mt < 2; mt++)
                ldsm4(af[mt][0], af[mt][1], af[mt][2], af[mt][3],
                      stg + aoff0 + (uint32_t)mt*2048 + csw);
#pragma unroll
            for (int p = 0; p < 4; p++)
                ldsm4t(bf[2*p][0], bf[2*p+1][0], bf[2*p][1], bf[2*p+1][1],
                       stg + bsl[p] + (uint32_t)(ks << 8));
#pragma unroll
            for (int mt = 0; mt < 2; mt++)
#pragma unroll
                for (int nt = 0; nt < 8; nt++) {
                    asm volatile(
                        "mma.sync.aligned.m16n8k16.row.col.f32.f16.f16.f32 "
                        "{%0,%1,%2,%3}, {%4,%5,%6,%7}, {%8,%9}, {%0,%1,%2,%3};"
                        : "+f"(acc[mt][nt][0]), "+f"(acc[mt][nt][1]),
                          "+f"(acc[mt][nt][2]), "+f"(acc[mt][nt][3])
                        : "r"(af[mt][0]), "r"(af[mt][1]), "r"(af[mt][2]), "r"(af[mt][3]),
                          "r"(bf[nt][0]), "r"(bf[nt][1]));
                }
        }
    }

    // ---- epilogue ----
    int q  = lane & 3;
    int gg = lane >> 2;
#pragma unroll
    for (int mt = 0; mt < 2; mt++) {
        int mrow = wm + mt*16 + gg;
        int t0 = arow[mrow], t1 = arow[mrow + 8];
        float w0 = 0.f, w1v = 0.f;
        if (MODE == 2) {
            w0  = (t0 >= 0) ? g_tv[t0] : 0.f;
            w1v = (t1 >= 0) ? g_tv[t1] : 0.f;
        }
#pragma unroll
        for (int nt = 0; nt < 8; nt++) {
            int col  = n0 + wn + nt*8 + 2*q;
            float bc0 = bias[e * outN + col];
            float bc1 = bias[e * outN + col + 1];
            float v00 = acc[mt][nt][0] + bc0;
            float v01 = acc[mt][nt][1] + bc1;
            float v10 = acc[mt][nt][2] + bc0;
            float v11 = acc[mt][nt][3] + bc1;
            if (MODE == 1) {
                size_t o0 = ((size_t)(e * CAP + m0 + mrow)) * outN + col;
                size_t o1 = o0 + (size_t)8 * outN;
                *(uint32_t*)(g_hh + o0) = pack_h2(fmaxf(v00, 0.f), fmaxf(v01, 0.f));
                *(uint32_t*)(g_hh + o1) = pack_h2(fmaxf(v10, 0.f), fmaxf(v11, 0.f));
            } else {
                if (t0 >= 0) {
                    float* p0 = out + (size_t)t0 * CC + col;
                    atomicAdd(p0,     w0 * v00);
                    atomicAdd(p0 + 1, w0 * v01);
                }
                if (t1 >= 0) {
                    float* p1 = out + (size_t)t1 * CC + col;
                    atomicAdd(p1,     w1v * v10);
                    atomicAdd(p1 + 1, w1v * v11);
                }
            }
        }
    }
}

// ---------------- aux loss ----------------
__global__ void aux_k(float* __restrict__ out, int out_size) {
    int lane = threadIdx.x;
    float v = 0.f;
    if (lane < EE)
        v = (g_imp[lane] / (float)NN) * ((float)g_cnt[lane] / (float)(NN * KKK));
#pragma unroll
    for (int off = 16; off; off >>= 1) v += __shfl_xor_sync(0xffffffffu, v, off);
    if (lane == 0) {
        if (out_size > NN * CC)     out[(size_t)NN * CC] = v;
        if (out_size - 1 > NN * CC) out[(size_t)out_size - 1] = v;
    }
}

// ---------------- launch ----------------
extern "C" void kernel_launch(void* const* d_in, const int* in_sizes, int n_in,
                              void* d_out, int out_size) {
    const float* x  = (const float*)d_in[0];
    const float* rw = (const float*)d_in[1];
    const float* rb = (const float*)d_in[2];
    const float* w1 = (const float*)d_in[3];
    const float* b1 = (const float*)d_in[4];
    const float* w2 = (const float*)d_in[5];
    const float* b2 = (const float*)d_in[6];
    float* out = (float*)d_out;

    static cudaStream_t s2 = nullptr;
    static cudaEvent_t evStart = nullptr, evW1 = nullptr, evW2 = nullptr;
    if (!s2) {
        cudaStreamCreateWithFlags(&s2, cudaStreamNonBlocking);
        cudaEventCreateWithFlags(&evStart, cudaEventDisableTiming);
        cudaEventCreateWithFlags(&evW1,   cudaEventDisableTiming);
        cudaEventCreateWithFlags(&evW2,   cudaEventDisableTiming);
    }

    cudaFuncSetAttribute(gemm_k<1>, cudaFuncAttributeMaxDynamicSharedMemorySize, SMEM_BYTES);
    cudaFuncSetAttribute(gemm_k<2>, cudaFuncAttributeMaxDynamicSharedMemorySize, SMEM_BYTES);

    __half* w1h; cudaGetSymbolAddress((void**)&w1h, g_w1h);
    __half* w2h; cudaGetSymbolAddress((void**)&w2h, g_w2h);

    // fork s2 off the (captured) main stream
    cudaEventRecord(evStart, 0);
    cudaStreamWaitEvent(s2, evStart, 0);

    // s2: weight conversions
    {
        int n8 = (int)((size_t)EE * CC * HH / 8);
        cvt_h<<<(n8 + 255) / 256, 256, 0, s2>>>((const float4*)w1, (uint4*)w1h, n8);
        cudaEventRecord(evW1, s2);
        cvt_h<<<(n8 + 255) / 256, 256, 0, s2>>>((const float4*)w2, (uint4*)w2h, n8);
        cudaEventRecord(evW2, s2);
    }

    // main: router (+x->fp16) and output zeroing
    init_k<<<1, 32>>>();
    router_k<<<NN / 8, 256>>>(x, rw, rb);
    cudaMemsetAsync(d_out, 0, (size_t)out_size * sizeof(float));

    // gemm1 needs router + w1h
    cudaStreamWaitEvent(0, evW1, 0);
    gemm_k<1><<<dim3(HH / BN, CAP / BM, EE), 256, SMEM_BYTES>>>(b1, nullptr);
    // gemm2 additionally needs w2h
    cudaStreamWaitEvent(0, evW2, 0);
    gemm_k<2><<<dim3(CC / BN, CAP / BM, EE), 256, SMEM_BYTES>>>(b2, out);
    aux_k<<<1, 32>>>(out, out_size);
}

// round 14
// speedup vs baseline: 1.2609x; 1.0445x over previous
#include <cuda_runtime.h>
#include <cuda_fp16.h>
#include <cstdint>
#include <math.h>

#define BB 4
#define TT 4096
#define CC 1024
#define EE 8
#define KKK 2
#define HH 4096
#define NN (BB*TT)
#define CAP 8192

#define BM 128
#define BN 128
#define BK 64                               // k-depth per stage
#define STAGES 3
#define A_BYTES (BM*128)                    // 128 token-rows x 128B (64 halves)
#define B_BYTES (BK*256)                    // 64 k-rows x 256B (128 halves)
#define STAGE_BYTES (A_BYTES + B_BYTES)     // 32768
#define SMEM_BYTES (STAGES*STAGE_BYTES)     // 98304

// ---------------- device scratch ----------------
__device__ int    g_cnt[EE];
__device__ float  g_imp[EE];
__device__ int    g_rows[EE*CAP];
__device__ int    g_tokrow[NN*KKK];
__device__ float  g_tv[NN*KKK];
__device__ __half g_hh[(size_t)EE*CAP*HH];     // intermediate (fp16)
__device__ __half g_xh[(size_t)NN*CC];         // fp16 x (written by router)
__device__ __half g_w1h[(size_t)EE*CC*HH];     // fp16 w1, native [e][k=C][n=H]
__device__ __half g_w2h[(size_t)EE*HH*CC];     // fp16 w2, native [e][k=H][n=C]

__device__ __forceinline__ uint32_t pack_h2(float lo, float hi) {
    union { __half2 h; uint32_t u; } cv;
    cv.h = __floats2half2_rn(lo, hi);
    return cv.u;
}
__device__ __forceinline__ void cp16(uint32_t dst, const void* src) {
    asm volatile("cp.async.cg.shared.global [%0], [%1], 16;\n" :: "r"(dst), "l"(src));
}
__device__ __forceinline__ void cp_commit() {
    asm volatile("cp.async.commit_group;\n" ::: "memory");
}
template<int N> __device__ __forceinline__ void cp_wait() {
    asm volatile("cp.async.wait_group %0;\n" :: "n"(N) : "memory");
}
__device__ __forceinline__ void ldsm4(uint32_t& r0, uint32_t& r1, uint32_t& r2, uint32_t& r3,
                                      uint32_t addr) {
    asm volatile("ldmatrix.sync.aligned.m8n8.x4.shared.b16 {%0,%1,%2,%3}, [%4];"
        : "=r"(r0), "=r"(r1), "=r"(r2), "=r"(r3) : "r"(addr));
}
__device__ __forceinline__ void ldsm4t(uint32_t& r0, uint32_t& r1, uint32_t& r2, uint32_t& r3,
                                       uint32_t addr) {
    asm volatile("ldmatrix.sync.aligned.m8n8.x4.trans.shared.b16 {%0,%1,%2,%3}, [%4];"
        : "=r"(r0), "=r"(r1), "=r"(r2), "=r"(r3) : "r"(addr));
}

// ---------------- init ----------------
__global__ void init_k() {
    int i = threadIdx.x;
    if (i < EE) { g_cnt[i] = 0; g_imp[i] = 0.f; }
}

// ---------------- fp32 -> fp16 streaming convert (weights) ----------------
__global__ void cvt_h(const float4* __restrict__ src, uint4* __restrict__ dst, int n8) {
    int i = blockIdx.x * blockDim.x + threadIdx.x;
    if (i >= n8) return;
    float4 a = src[2*i], b = src[2*i+1];
    uint4 o;
    o.x = pack_h2(a.x, a.y);
    o.y = pack_h2(a.z, a.w);
    o.z = pack_h2(b.x, b.y);
    o.w = pack_h2(b.z, b.w);
    dst[i] = o;
}

// ---------------- router: rw staged in smem (pitch 9 = conflict-free) -------
__global__ void router_k(const float* __restrict__ x,
                         const float* __restrict__ rw,
                         const float* __restrict__ rb) {
    __shared__ float srw[CC * 9];              // srw[c*9 + e], 36 KB
    __shared__ float simp[EE];
    __shared__ int   scnt[EE];
    __shared__ int   sbase[EE];
    __shared__ int   tok_e[8][2];
    __shared__ int   tok_lp[8][2];

    int tid  = threadIdx.x;
    int w    = tid >> 5;
    int lane = tid & 31;
    int gw   = blockIdx.x * 8 + w;

    if (tid < EE) { simp[tid] = 0.f; scnt[tid] = 0; }
    // stage rw: 8192 floats, coalesced read, pitched store
    for (int idx = tid; idx < CC * EE; idx += 256) {
        int c = idx >> 3, e = idx & 7;
        srw[c * 9 + e] = rw[idx];
    }
    __syncthreads();

    const float* xr = x + (size_t)gw * CC;
    __half* xh = g_xh + (size_t)gw * CC;

    float acc[EE];
#pragma unroll
    for (int e = 0; e < EE; e++) acc[e] = 0.f;

#pragma unroll 4
    for (int i = 0; i < CC/32; i++) {           // 32 iterations
        int c = i*32 + lane;
        float xv = xr[c];
        xh[c] = __float2half_rn(xv);
        const float* wr = &srw[c * 9];
#pragma unroll
        for (int e = 0; e < EE; e++) acc[e] = fmaf(xv, wr[e], acc[e]);
    }
#pragma unroll
    for (int e = 0; e < EE; e++) {
#pragma unroll
        for (int off = 16; off; off >>= 1)
            acc[e] += __shfl_xor_sync(0xffffffffu, acc[e], off);
    }
    if (lane == 0) {
        float p[EE];
        float mx = -1e30f;
#pragma unroll
        for (int e = 0; e < EE; e++) { p[e] = acc[e] + rb[e]; mx = fmaxf(mx, p[e]); }
        float s = 0.f;
#pragma unroll
        for (int e = 0; e < EE; e++) { p[e] = expf(p[e] - mx); s += p[e]; }
        float inv = 1.f / s;
#pragma unroll
        for (int e = 0; e < EE; e++) p[e] *= inv;

        int i0 = 0;
#pragma unroll
        for (int e = 1; e < EE; e++) if (p[e] > p[i0]) i0 = e;
        int i1 = (i0 == 0) ? 1 : 0;
#pragma unroll
        for (int e = 0; e < EE; e++) if (e != i0 && p[e] > p[i1]) i1 = e;

        g_tv[gw*2]   = p[i0];
        g_tv[gw*2+1] = p[i1];
        int es[2] = { i0, i1 };
#pragma unroll
        for (int s2 = 0; s2 < 2; s2++) {
            int e = es[s2];
            tok_e[w][s2]  = e;
            tok_lp[w][s2] = atomicAdd(&scnt[e], 1);
        }
#pragma unroll
        for (int e = 0; e < EE; e++) atomicAdd(&simp[e], p[e]);
    }
    __syncthreads();
    if (tid < EE) {
        sbase[tid] = atomicAdd(&g_cnt[tid], scnt[tid]);
        atomicAdd(&g_imp[tid], simp[tid]);
    }
    __syncthreads();
    if (tid < 16) {
        int wt = tid >> 1, s2 = tid & 1;
        int e   = tok_e[wt][s2];
        int pos = sbase[e] + tok_lp[wt][s2];
        int gt  = blockIdx.x * 8 + wt;
        if (pos < CAP) {
            g_rows[e*CAP + pos]  = gt;
            g_tokrow[gt*2 + s2]  = e*CAP + pos;
        } else {
            g_tokrow[gt*2 + s2]  = -1;
        }
    }
}

// ---------------- grouped GEMM, fp16 m16n8k16, B via ldmatrix.trans ----------
// MODE 1: h = relu(gather(xh) @ w1[e] + b1[e])  -> fp16 (g_hh)
// MODE 2: out[tok] += w_tok * (h @ w2[e] + b2[e])   (atomic combine)
template<int MODE>
__global__ __launch_bounds__(256, 2)
void gemm_k(const float* __restrict__ bias, float* __restrict__ out) {
    constexpr int  Kdim  = (MODE == 1) ? CC : HH;
    constexpr int  outN  = (MODE == 1) ? HH : CC;
    constexpr int  ITERS = Kdim / BK;

    const __half* A = (MODE == 1) ? g_xh : g_hh;
    const __half* W = (MODE == 1) ? g_w1h : g_w2h;

    int e   = blockIdx.z;
    int cnt = min(g_cnt[e], CAP);
    int m0  = blockIdx.y * BM;
    if (m0 >= cnt) return;
    int n0  = blockIdx.x * BN;

    extern __shared__ char smem[];
    __shared__ int arow[BM];

    int tid  = threadIdx.x;
    int lane = tid & 31, warp = tid >> 5;

    if (tid < BM) {
        int idx = m0 + tid;
        if (MODE == 1) arow[tid] = (idx < cnt) ? g_rows[e*CAP + idx] : 0;
        else           arow[tid] = (idx < cnt) ? g_rows[e*CAP + idx] : -1;
    }
    __syncthreads();

    // ---- cp.async descriptors ----
    int j  = tid & 7;
    int rT = tid >> 3;                 // 0..31
    uint32_t adst0 = (uint32_t)(rT*128 + ((j ^ (rT & 7)) << 4));
    const __half* Aj = A + j*8;
    int j2 = tid & 15;
    int rB = tid >> 4;                 // 0..15
    uint32_t bdst0 = (uint32_t)(A_BYTES + rB*256 + ((j2 ^ (rB & 7)) << 4));
    const __half* Bj = W + (size_t)e * Kdim * outN + n0 + j2*8;

    uint32_t smbase = (uint32_t)__cvta_generic_to_shared(smem);

    auto issue = [&](int stage, int it) {
        uint32_t s = smbase + (uint32_t)stage * STAGE_BYTES;
        size_t koff = (size_t)it * BK;
#pragma unroll
        for (int i = 0; i < 4; i++) {
            int r = rT + 32*i;
            size_t ar = (MODE == 1) ? (size_t)arow[r] : (size_t)(e*CAP + m0 + r);
            cp16(s + adst0 + (uint32_t)i*4096, Aj + ar * Kdim + koff);
        }
#pragma unroll
        for (int i = 0; i < 4; i++)
            cp16(s + bdst0 + (uint32_t)i*4096, Bj + (koff + (size_t)(rB + 16*i)) * outN);
    };

    issue(0, 0); cp_commit();
    issue(1, 1); cp_commit();

    // ---- ldmatrix per-lane components ----
    int wm  = (warp & 3) * 32;
    int wn  = (warp >> 2) * 64;
    int r16 = lane & 15;
    int coff = lane >> 4;
    int sl7  = lane & 7;
    uint32_t aoff0 = (uint32_t)((wm + r16) * 128);
    int sub = lane & 7;
    int mi  = lane >> 3;
    int kl  = ((mi >> 1) << 3) + sub;     // 0..15
    int slotbit = mi & 1;
    uint32_t bsl[4];
#pragma unroll
    for (int p = 0; p < 4; p++) {
        int slot = (wn >> 3) + 2*p + slotbit;
        bsl[p] = (uint32_t)(A_BYTES + kl*256 + ((slot ^ sub) << 4));
    }

    float acc[2][8][4];
#pragma unroll
    for (int mt = 0; mt < 2; mt++)
#pragma unroll
        for (int nt = 0; nt < 8; nt++)
#pragma unroll
            for (int q = 0; q < 4; q++) acc[mt][nt][q] = 0.f;

    for (int it = 0; it < ITERS; ++it) {
        cp_wait<1>();
        __syncthreads();
        if (it + 2 < ITERS) issue((it + 2) % STAGES, it + 2);
        cp_commit();

        uint32_t stg = smbase + (uint32_t)(it % STAGES) * STAGE_BYTES;

#pragma unroll
        for (int ks = 0; ks < BK; ks += 16) {
            const int c0 = (ks >> 3) + coff;
            const uint32_t csw = (uint32_t)((c0 ^ sl7) << 4);
            uint32_t af[2][4], bf[8][2];
#pragma unroll
            for (int mt = 0; mt < 2; mt++)
                ldsm4(af[mt][0], af[mt][1], af[mt][2], af[mt][3],
                      stg + aoff0 + (uint32_t)mt*2048 + csw);
#pragma unroll
            for (int p = 0; p < 4; p++)
                ldsm4t(bf[2*p][0], bf[2*p+1][0], bf[2*p][1], bf[2*p+1][1],
                       stg + bsl[p] + (uint32_t)(ks << 8));
#pragma unroll
            for (int mt = 0; mt < 2; mt++)
#pragma unroll
                for (int nt = 0; nt < 8; nt++) {
                    asm volatile(
                        "mma.sync.aligned.m16n8k16.row.col.f32.f16.f16.f32 "
                        "{%0,%1,%2,%3}, {%4,%5,%6,%7}, {%8,%9}, {%0,%1,%2,%3};"
                        : "+f"(acc[mt][nt][0]), "+f"(acc[mt][nt][1]),
                          "+f"(acc[mt][nt][2]), "+f"(acc[mt][nt][3])
                        : "r"(af[mt][0]), "r"(af[mt][1]), "r"(af[mt][2]), "r"(af[mt][3]),
                          "r"(bf[nt][0]), "r"(bf[nt][1]));
                }
        }
    }

    // ---- epilogue ----
    int q  = lane & 3;
    int gg = lane >> 2;
#pragma unroll
    for (int mt = 0; mt < 2; mt++) {
        int mrow = wm + mt*16 + gg;
        int t0 = arow[mrow], t1 = arow[mrow + 8];
        float w0 = 0.f, w1v = 0.f;
        if (MODE == 2) {
            w0  = (t0 >= 0) ? g_tv[t0] : 0.f;
            w1v = (t1 >= 0) ? g_tv[t1] : 0.f;
        }
#pragma unroll
        for (int nt = 0; nt < 8; nt++) {
            int col  = n0 + wn + nt*8 + 2*q;
            float bc0 = bias[e * outN + col];
            float bc1 = bias[e * outN + col + 1];
            float v00 = acc[mt][nt][0] + bc0;
            float v01 = acc[mt][nt][1] + bc1;
            float v10 = acc[mt][nt][2] + bc0;
            float v11 = acc[mt][nt][3] + bc1;
            if (MODE == 1) {
                size_t o0 = ((size_t)(e * CAP + m0 + mrow)) * outN + col;
                size_t o1 = o0 + (size_t)8 * outN;
                *(uint32_t*)(g_hh + o0) = pack_h2(fmaxf(v00, 0.f), fmaxf(v01, 0.f));
                *(uint32_t*)(g_hh + o1) = pack_h2(fmaxf(v10, 0.f), fmaxf(v11, 0.f));
            } else {
                if (t0 >= 0) {
                    float* p0 = out + (size_t)t0 * CC + col;
                    atomicAdd(p0,     w0 * v00);
                    atomicAdd(p0 + 1, w0 * v01);
                }
                if (t1 >= 0) {
                    float* p1 = out + (size_t)t1 * CC + col;
                    atomicAdd(p1,     w1v * v10);
                    atomicAdd(p1 + 1, w1v * v11);
                }
            }
        }
    }
}

// ---------------- aux loss ----------------
__global__ void aux_k(float* __restrict__ out, int out_size) {
    int lane = threadIdx.x;
    float v = 0.f;
    if (lane < EE)
        v = (g_imp[lane] / (float)NN) * ((float)g_cnt[lane] / (float)(NN * KKK));
#pragma unroll
    for (int off = 16; off; off >>= 1) v += __shfl_xor_sync(0xffffffffu, v, off);
    if (lane == 0) {
        if (out_size > NN * CC)     out[(size_t)NN * CC] = v;
        if (out_size - 1 > NN * CC) out[(size_t)out_size - 1] = v;
    }
}

// ---------------- launch ----------------
extern "C" void kernel_launch(void* const* d_in, const int* in_sizes, int n_in,
                              void* d_out, int out_size) {
    const float* x  = (const float*)d_in[0];
    const float* rw = (const float*)d_in[1];
    const float* rb = (const float*)d_in[2];
    const float* w1 = (const float*)d_in[3];
    const float* b1 = (const float*)d_in[4];
    const float* w2 = (const float*)d_in[5];
    const float* b2 = (const float*)d_in[6];
    float* out = (float*)d_out;

    static cudaStream_t s2 = nullptr;
    static cudaEvent_t evStart = nullptr, evW1 = nullptr, evW2 = nullptr;
    if (!s2) {
        cudaStreamCreateWithFlags(&s2, cudaStreamNonBlocking);
        cudaEventCreateWithFlags(&evStart, cudaEventDisableTiming);
        cudaEventCreateWithFlags(&evW1,   cudaEventDisableTiming);
        cudaEventCreateWithFlags(&evW2,   cudaEventDisableTiming);
    }

    cudaFuncSetAttribute(gemm_k<1>, cudaFuncAttributeMaxDynamicSharedMemorySize, SMEM_BYTES);
    cudaFuncSetAttribute(gemm_k<2>, cudaFuncAttributeMaxDynamicSharedMemorySize, SMEM_BYTES);

    __half* w1h; cudaGetSymbolAddress((void**)&w1h, g_w1h);
    __half* w2h; cudaGetSymbolAddress((void**)&w2h, g_w2h);

    // fork s2 off the (captured) main stream
    cudaEventRecord(evStart, 0);
    cudaStreamWaitEvent(s2, evStart, 0);

    // s2: weight conversions
    {
        int n8 = (int)((size_t)EE * CC * HH / 8);
        cvt_h<<<(n8 + 255) / 256, 256, 0, s2>>>((const float4*)w1, (uint4*)w1h, n8);
        cudaEventRecord(evW1, s2);
        cvt_h<<<(n8 + 255) / 256, 256, 0, s2>>>((const float4*)w2, (uint4*)w2h, n8);
        cudaEventRecord(evW2, s2);
    }

    // main: router (+x->fp16) and output zeroing
    init_k<<<1, 32>>>();
    router_k<<<NN / 8, 256>>>(x, rw, rb);
    cudaMemsetAsync(d_out, 0, (size_t)out_size * sizeof(float));

    // gemm1 needs router + w1h
    cudaStreamWaitEvent(0, evW1, 0);
    gemm_k<1><<<dim3(HH / BN, CAP / BM, EE), 256, SMEM_BYTES>>>(b1, nullptr);
    // gemm2 additionally needs w2h
    cudaStreamWaitEvent(0, evW2, 0);
    gemm_k<2><<<dim3(CC / BN, CAP / BM, EE), 256, SMEM_BYTES>>>(b2, out);
    aux_k<<<1, 32>>>(out, out_size);
}